// round 1
// baseline (speedup 1.0000x reference)
#include <cuda_runtime.h>

// ---------------------------------------------------------------------------
// ModulatedAttLayer  B=256, C=2048, H=W=7 (N=49), INTER=1024
//
// Pipeline:
//   K1 transpose:  x[B,C,N]          -> xT[B,N,C]
//   K2 proj (x3):  xT @ w^T + b      -> gx/tx/px  [B*N, 1024]   (SGEMM 12544x1024x2048)
//   K3 attn:       scores=tx@px^T, softmax, map = attn @ gx -> d_map [B,N,1024]
//   K4 spart:      partial spatial FC  x_flat @ fc_w^T (k-split 16)
//   K5 sred:       reduce partials + fc_b -> d_sp [B,49]
//   K6 mask+out:   out = x + sp[b,n] * (W_w @ map)   (per-batch GEMM 2048x49x1024)
// ---------------------------------------------------------------------------

#define BB   256
#define CC   2048
#define NN   49
#define II   1024
#define CN   (CC*NN)      // 100352
#define KSPL 16
#define KPER (CN/KSPL)    // 6272

__device__ float d_xT[(size_t)BB*NN*CC];       // 102.8 MB
__device__ float d_gx[(size_t)BB*NN*II];       // 51.4 MB
__device__ float d_tx[(size_t)BB*NN*II];
__device__ float d_px[(size_t)BB*NN*II];
__device__ float d_map[(size_t)BB*NN*II];
__device__ float d_spart[(size_t)KSPL*BB*NN];
__device__ float d_sp[(size_t)BB*NN];

// ---------------- K1: transpose x[b,c,n] -> xT[b,n,c] ----------------------
__global__ void k_transpose(const float* __restrict__ x) {
    __shared__ float s[64][50];
    int b = blockIdx.y, c0 = blockIdx.x * 64;
    const float* xb = x + (size_t)b * CN;
    for (int e = threadIdx.x; e < 64 * NN; e += 256) {
        int cl = e / NN, n = e - cl * NN;
        s[cl][n] = xb[(c0 + cl) * NN + n];
    }
    __syncthreads();
    float* o = d_xT + (size_t)b * NN * CC;
    for (int e = threadIdx.x; e < 64 * NN; e += 256) {
        int n = e >> 6, cl = e & 63;
        o[n * CC + c0 + cl] = s[cl][n];
    }
}

// ---------------- K2: SGEMM  out[m,o] = sum_k xT[m,k]*w[o,k] + bias[o] -----
// M=12544, K=2048, N=1024.  128x128 tile, kt=16, 256 thr, 8x8 per thread.
__global__ void __launch_bounds__(256) k_proj(const float* __restrict__ w,
                                              const float* __restrict__ bias,
                                              int sel) {
    __shared__ float As[16][128];
    __shared__ float Bs[16][128];
    float* out = (sel == 0) ? d_gx : (sel == 1) ? d_tx : d_px;

    int m0 = blockIdx.y * 128, n0 = blockIdx.x * 128;
    int tid = threadIdx.x;
    int txl = tid & 15, tyl = tid >> 4;
    float acc[8][8] = {};

    for (int k0 = 0; k0 < CC; k0 += 16) {
        #pragma unroll
        for (int i = 0; i < 2; i++) {
            int f = tid + i * 256;
            int row = f >> 2, kq = (f & 3) * 4;
            float4 av = *(const float4*)(d_xT + (size_t)(m0 + row) * CC + k0 + kq);
            As[kq + 0][row] = av.x; As[kq + 1][row] = av.y;
            As[kq + 2][row] = av.z; As[kq + 3][row] = av.w;
            float4 bv = *(const float4*)(w + (size_t)(n0 + row) * CC + k0 + kq);
            Bs[kq + 0][row] = bv.x; Bs[kq + 1][row] = bv.y;
            Bs[kq + 2][row] = bv.z; Bs[kq + 3][row] = bv.w;
        }
        __syncthreads();
        #pragma unroll
        for (int kk = 0; kk < 16; kk++) {
            float a[8], bvr[8];
            *(float4*)(a)     = *(float4*)&As[kk][tyl * 8];
            *(float4*)(a + 4) = *(float4*)&As[kk][tyl * 8 + 4];
            *(float4*)(bvr)     = *(float4*)&Bs[kk][txl * 8];
            *(float4*)(bvr + 4) = *(float4*)&Bs[kk][txl * 8 + 4];
            #pragma unroll
            for (int i = 0; i < 8; i++)
                #pragma unroll
                for (int j = 0; j < 8; j++)
                    acc[i][j] += a[i] * bvr[j];
        }
        __syncthreads();
    }
    #pragma unroll
    for (int i = 0; i < 8; i++) {
        int m = m0 + tyl * 8 + i;
        float* op = out + (size_t)m * II + n0 + txl * 8;
        #pragma unroll
        for (int j = 0; j < 8; j++)
            op[j] = acc[i][j] + bias[n0 + txl * 8 + j];
    }
}

// ---------------- K3: attention per batch ----------------------------------
// 256 threads = 4 k-groups x 64 threads; each group does a k-quarter of
// scores = tx @ px^T (49x49x1024), partials reduced in smem; softmax; then
// map[b,n,o] = sum_m attn[n,m] * gx[b,m,o].
__global__ void __launch_bounds__(256) k_attn() {
    __shared__ float th_s[4][49][17];
    __shared__ float ph_s[4][49][17];
    __shared__ float sc[49][52];

    int b = blockIdx.x;
    int tid = threadIdx.x;
    int g = tid >> 6, t = tid & 63;
    int ng = t >> 3, mg = t & 7;
    bool act = (ng < 7) && (mg < 7);

    float acc[7][7] = {};
    for (int kt = 0; kt < 16; kt++) {
        int kb = g * 256 + kt * 16;
        for (int e = t; e < 49 * 16; e += 64) {
            int r = e >> 4, kk = e & 15;
            th_s[g][r][kk] = d_tx[((size_t)b * NN + r) * II + kb + kk];
            ph_s[g][r][kk] = d_px[((size_t)b * NN + r) * II + kb + kk];
        }
        __syncthreads();
        if (act) {
            #pragma unroll
            for (int kk = 0; kk < 16; kk++) {
                float av[7], bv[7];
                #pragma unroll
                for (int i = 0; i < 7; i++) av[i] = th_s[g][ng * 7 + i][kk];
                #pragma unroll
                for (int j = 0; j < 7; j++) bv[j] = ph_s[g][mg * 7 + j][kk];
                #pragma unroll
                for (int i = 0; i < 7; i++)
                    #pragma unroll
                    for (int j = 0; j < 7; j++)
                        acc[i][j] += av[i] * bv[j];
            }
        }
        __syncthreads();
    }
    // reduce 4 k-group partials sequentially
    for (int gg = 0; gg < 4; gg++) {
        if (g == gg && act) {
            #pragma unroll
            for (int i = 0; i < 7; i++)
                #pragma unroll
                for (int j = 0; j < 7; j++) {
                    if (gg == 0) sc[ng * 7 + i][mg * 7 + j] = acc[i][j];
                    else         sc[ng * 7 + i][mg * 7 + j] += acc[i][j];
                }
        }
        __syncthreads();
    }
    // softmax rows (49 threads)
    if (tid < 49) {
        float mx = -1e30f;
        for (int m = 0; m < NN; m++) mx = fmaxf(mx, sc[tid][m]);
        float s = 0.f;
        for (int m = 0; m < NN; m++) {
            float e = expf(sc[tid][m] - mx);
            sc[tid][m] = e; s += e;
        }
        float inv = 1.f / s;
        for (int m = 0; m < NN; m++) sc[tid][m] *= inv;
    }
    __syncthreads();
    // map = attn @ gx   (each thread owns one output column o, all 49 n)
    for (int op = 0; op < 4; op++) {
        int o = op * 256 + tid;
        float a2[49];
        #pragma unroll
        for (int n = 0; n < NN; n++) a2[n] = 0.f;
        for (int m = 0; m < NN; m++) {
            float gv = d_gx[((size_t)b * NN + m) * II + o];
            #pragma unroll
            for (int n = 0; n < NN; n++) a2[n] += sc[n][m] * gv;
        }
        for (int n = 0; n < NN; n++)
            d_map[((size_t)b * NN + n) * II + o] = a2[n];
    }
}

// ---------------- K4: spatial FC partials -----------------------------------
// grid (16 batch-tiles, 16 k-splits). Block: 16 batches x 49 outputs over
// KPER=6272 k. threads 256 = 8 bgrp x 32 jgrp, each owns 2b x 2j.
__global__ void __launch_bounds__(256) k_spart(const float* __restrict__ x,
                                               const float* __restrict__ fcw) {
    __shared__ float fc_s[49][65];
    __shared__ float x_s[16][65];
    int b0 = blockIdx.x * 16;
    int ks = blockIdx.y;
    int tid = threadIdx.x;
    int bg = tid >> 5, jg = tid & 31;
    float acc[2][2] = {};
    for (int kc = 0; kc < KPER / 64; kc++) {
        int kb = ks * KPER + kc * 64;
        for (int e = tid; e < 49 * 64; e += 256) {
            int j = e >> 6, kk = e & 63;
            fc_s[j][kk] = fcw[(size_t)j * CN + kb + kk];
        }
        for (int e = tid; e < 16 * 64; e += 256) {
            int bl = e >> 6, kk = e & 63;
            x_s[bl][kk] = x[(size_t)(b0 + bl) * CN + kb + kk];
        }
        __syncthreads();
        #pragma unroll 8
        for (int kk = 0; kk < 64; kk++) {
            float x0 = x_s[bg * 2][kk], x1 = x_s[bg * 2 + 1][kk];
            float f0 = fc_s[jg][kk];
            float f1 = (jg < 17) ? fc_s[jg + 32][kk] : 0.f;
            acc[0][0] += x0 * f0; acc[0][1] += x0 * f1;
            acc[1][0] += x1 * f0; acc[1][1] += x1 * f1;
        }
        __syncthreads();
    }
    #pragma unroll
    for (int i = 0; i < 2; i++) {
        int b = b0 + bg * 2 + i;
        d_spart[((size_t)ks * BB + b) * NN + jg] = acc[i][0];
        if (jg + 32 < NN)
            d_spart[((size_t)ks * BB + b) * NN + jg + 32] = acc[i][1];
    }
}

// ---------------- K5: reduce k-split partials + bias ------------------------
__global__ void k_sred(const float* __restrict__ fcb) {
    int b = blockIdx.x, j = threadIdx.x;
    if (j < NN) {
        float s = fcb[j];
        for (int ks = 0; ks < KSPL; ks++)
            s += d_spart[((size_t)ks * BB + b) * NN + j];
        d_sp[b * NN + j] = s;
    }
}

// ---------------- K6: mask GEMM + epilogue -----------------------------------
// out[b,c,n] = x[b,c,n] + sp[b,n] * sum_o W_w[c,o]*map[b,n,o]
// grid (16 c-tiles, 256 b). 256 thr = 32 cgrp x 8 ngrp; thread owns 4c x 7n.
__global__ void __launch_bounds__(256) k_mask(const float* __restrict__ x,
                                              const float* __restrict__ Ww,
                                              float* __restrict__ out) {
    __shared__ float W_s[32][130];
    __shared__ float m_s[32][56];
    __shared__ float sp_s[NN];
    int c0 = blockIdx.x * 128, b = blockIdx.y;
    int tid = threadIdx.x;
    if (tid < NN) sp_s[tid] = d_sp[b * NN + tid];
    int cg = tid >> 3, ngr = tid & 7;
    float acc[4][7] = {};
    for (int ot = 0; ot < II / 32; ot++) {
        int o0 = ot * 32;
        for (int e = tid; e < 128 * 32; e += 256) {
            int cl = e >> 5, kk = e & 31;
            W_s[kk][cl] = Ww[(size_t)(c0 + cl) * II + o0 + kk];
        }
        for (int e = tid; e < 49 * 32; e += 256) {
            int n = e >> 5, kk = e & 31;
            m_s[kk][n] = d_map[((size_t)b * NN + n) * II + o0 + kk];
        }
        __syncthreads();
        if (ngr < 7) {
            #pragma unroll 8
            for (int kk = 0; kk < 32; kk++) {
                float wv[4], mv[7];
                #pragma unroll
                for (int i = 0; i < 4; i++) wv[i] = W_s[kk][cg * 4 + i];
                #pragma unroll
                for (int j = 0; j < 7; j++) mv[j] = m_s[kk][ngr * 7 + j];
                #pragma unroll
                for (int i = 0; i < 4; i++)
                    #pragma unroll
                    for (int j = 0; j < 7; j++)
                        acc[i][j] += wv[i] * mv[j];
            }
        }
        __syncthreads();
    }
    if (ngr < 7) {
        #pragma unroll
        for (int i = 0; i < 4; i++) {
            int c = c0 + cg * 4 + i;
            #pragma unroll
            for (int j = 0; j < 7; j++) {
                int n = ngr * 7 + j;
                size_t idx = ((size_t)b * CC + c) * NN + n;
                out[idx] = x[idx] + sp_s[n] * acc[i][j];
            }
        }
    }
}

// ---------------------------------------------------------------------------
extern "C" void kernel_launch(void* const* d_in, const int* in_sizes, int n_in,
                              void* d_out, int out_size) {
    const float* x    = (const float*)d_in[0];
    const float* g_w  = (const float*)d_in[1];
    const float* g_b  = (const float*)d_in[2];
    const float* th_w = (const float*)d_in[3];
    const float* th_b = (const float*)d_in[4];
    const float* ph_w = (const float*)d_in[5];
    const float* ph_b = (const float*)d_in[6];
    const float* W_w  = (const float*)d_in[7];
    const float* fc_w = (const float*)d_in[8];
    const float* fc_b = (const float*)d_in[9];
    float* out = (float*)d_out;
    (void)in_sizes; (void)n_in; (void)out_size;

    k_transpose<<<dim3(CC / 64, BB), 256>>>(x);

    dim3 pg(II / 128, (BB * NN) / 128);   // (8, 98)
    k_proj<<<pg, 256>>>(g_w,  g_b,  0);
    k_proj<<<pg, 256>>>(th_w, th_b, 1);
    k_proj<<<pg, 256>>>(ph_w, ph_b, 2);

    k_attn<<<BB, 256>>>();

    k_spart<<<dim3(BB / 16, KSPL), 256>>>(x, fc_w);
    k_sred<<<BB, 64>>>(fc_b);

    k_mask<<<dim3(CC / 128, BB), 256>>>(x, W_w, out);
}

// round 2
// speedup vs baseline: 1.7692x; 1.7692x over previous
#include <cuda_runtime.h>

// ---------------------------------------------------------------------------
// ModulatedAttLayer  B=256, C=2048, H=W=7 (N=49), INTER=1024
//
// R2: GEMMs on tensor cores (mma.sync m16n8k8 TF32).
//   - theta/phi projections: TF32x3 (hi/lo split) for softmax-critical precision
//   - g projection + mask GEMM: single TF32 (rna)
//   - attention (49x49) / spatial FC: fp32 (tiny / memory-bound)
// ---------------------------------------------------------------------------

#define BB   256
#define CC   2048
#define NN   49
#define II   1024
#define CN   (CC*NN)      // 100352
#define KSPL 16
#define KPER (CN/KSPL)    // 6272

__device__ float d_xT[(size_t)BB*NN*CC];
__device__ float d_gx[(size_t)BB*NN*II];
__device__ float d_tx[(size_t)BB*NN*II];
__device__ float d_px[(size_t)BB*NN*II];
__device__ float d_map[(size_t)BB*NN*II];
__device__ float d_spart[(size_t)KSPL*BB*NN];
__device__ float d_sp[(size_t)BB*NN];

// ---------------- tf32 helpers ----------------------------------------------
__device__ __forceinline__ unsigned f2tf(float v) {
    unsigned u;
    asm("cvt.rna.tf32.f32 %0, %1;" : "=r"(u) : "f"(v));
    return u;
}

__device__ __forceinline__ void mma8(float* d, const unsigned* a, const unsigned* b) {
    asm volatile(
        "mma.sync.aligned.m16n8k8.row.col.f32.tf32.tf32.f32 "
        "{%0,%1,%2,%3}, {%4,%5,%6,%7}, {%8,%9}, {%0,%1,%2,%3};\n"
        : "+f"(d[0]), "+f"(d[1]), "+f"(d[2]), "+f"(d[3])
        : "r"(a[0]), "r"(a[1]), "r"(a[2]), "r"(a[3]), "r"(b[0]), "r"(b[1]));
}

// ---------------- K1: transpose x[b,c,n] -> xT[b,n,c] ----------------------
__global__ void k_transpose(const float* __restrict__ x) {
    __shared__ float s[64][50];
    int b = blockIdx.y, c0 = blockIdx.x * 64;
    const float* xb = x + (size_t)b * CN;
    for (int e = threadIdx.x; e < 64 * NN; e += 256) {
        int cl = e / NN, n = e - cl * NN;
        s[cl][n] = xb[(c0 + cl) * NN + n];
    }
    __syncthreads();
    float* o = d_xT + (size_t)b * NN * CC;
    for (int e = threadIdx.x; e < 64 * NN; e += 256) {
        int n = e >> 6, cl = e & 63;
        o[n * CC + c0 + cl] = s[cl][n];
    }
}

// ---------------- GEMM core: acc[m,n] += A[m,k]*B[n,k] ----------------------
// CTA 128x128, kt=16, 8 warps (2m x 4n), warp tile 64x32.
// smem raw fp32 [row][k] padded stride 20 (conflict-free frag LDS);
// register prefetch of next k-tile overlaps compute.
template<int NSPLIT, int K>
__device__ __forceinline__ void gemm_core(const float* __restrict__ A,
                                          const float* __restrict__ Bm,
                                          int m0, int n0,
                                          float* As, float* Bs,
                                          float acc[4][4][4]) {
    const int tid = threadIdx.x, lane = tid & 31, wid = tid >> 5;
    const int wm = wid & 1, wn = wid >> 1;
    const int ar = lane >> 2, ak = lane & 3;

    const int row0 = tid >> 2,        kq0 = (tid & 3) * 4;
    const int row1 = (tid + 256) >> 2, kq1 = ((tid + 256) & 3) * 4;

    float4 ra0 = *(const float4*)(A  + (size_t)(m0 + row0) * K + kq0);
    float4 ra1 = *(const float4*)(A  + (size_t)(m0 + row1) * K + kq1);
    float4 rb0 = *(const float4*)(Bm + (size_t)(n0 + row0) * K + kq0);
    float4 rb1 = *(const float4*)(Bm + (size_t)(n0 + row1) * K + kq1);

    for (int k0 = 0; k0 < K; k0 += 16) {
        *(float4*)&As[row0 * 20 + kq0] = ra0;
        *(float4*)&As[row1 * 20 + kq1] = ra1;
        *(float4*)&Bs[row0 * 20 + kq0] = rb0;
        *(float4*)&Bs[row1 * 20 + kq1] = rb1;
        __syncthreads();

        if (k0 + 16 < K) {   // prefetch next tile (hides LDG behind mma)
            ra0 = *(const float4*)(A  + (size_t)(m0 + row0) * K + k0 + 16 + kq0);
            ra1 = *(const float4*)(A  + (size_t)(m0 + row1) * K + k0 + 16 + kq1);
            rb0 = *(const float4*)(Bm + (size_t)(n0 + row0) * K + k0 + 16 + kq0);
            rb1 = *(const float4*)(Bm + (size_t)(n0 + row1) * K + k0 + 16 + kq1);
        }

        #pragma unroll
        for (int ks = 0; ks < 16; ks += 8) {
            unsigned ah[4][4], al[4][4], bh[4][2], bl[4][2];
            #pragma unroll
            for (int mt = 0; mt < 4; mt++) {
                int r = (wm * 64 + mt * 16 + ar) * 20 + ks + ak;
                float v0 = As[r], v1 = As[r + 160], v2 = As[r + 4], v3 = As[r + 164];
                ah[mt][0] = f2tf(v0); ah[mt][1] = f2tf(v1);
                ah[mt][2] = f2tf(v2); ah[mt][3] = f2tf(v3);
                if constexpr (NSPLIT == 3) {
                    al[mt][0] = f2tf(v0 - __uint_as_float(ah[mt][0]));
                    al[mt][1] = f2tf(v1 - __uint_as_float(ah[mt][1]));
                    al[mt][2] = f2tf(v2 - __uint_as_float(ah[mt][2]));
                    al[mt][3] = f2tf(v3 - __uint_as_float(ah[mt][3]));
                }
            }
            #pragma unroll
            for (int nt = 0; nt < 4; nt++) {
                int c = (wn * 32 + nt * 8 + ar) * 20 + ks + ak;
                float v0 = Bs[c], v1 = Bs[c + 4];
                bh[nt][0] = f2tf(v0); bh[nt][1] = f2tf(v1);
                if constexpr (NSPLIT == 3) {
                    bl[nt][0] = f2tf(v0 - __uint_as_float(bh[nt][0]));
                    bl[nt][1] = f2tf(v1 - __uint_as_float(bh[nt][1]));
                }
            }
            #pragma unroll
            for (int mt = 0; mt < 4; mt++)
                #pragma unroll
                for (int nt = 0; nt < 4; nt++) {
                    if constexpr (NSPLIT == 3) {
                        mma8(acc[mt][nt], al[mt], bh[nt]);
                        mma8(acc[mt][nt], ah[mt], bl[nt]);
                    }
                    mma8(acc[mt][nt], ah[mt], bh[nt]);
                }
        }
        __syncthreads();
    }
}

// ---------------- K2: projections (M=12544, N=1024, K=2048) -----------------
template<int NSPLIT>
__global__ void __launch_bounds__(256) k_proj_mma(const float* __restrict__ w,
                                                  const float* __restrict__ bias,
                                                  float* __restrict__ out) {
    __shared__ float As[128 * 20];
    __shared__ float Bs[128 * 20];
    int n0 = blockIdx.x * 128, m0 = blockIdx.y * 128;
    float acc[4][4][4] = {};
    gemm_core<NSPLIT, CC>(d_xT, w, m0, n0, As, Bs, acc);

    int lane = threadIdx.x & 31, wid = threadIdx.x >> 5;
    int wm = wid & 1, wn = wid >> 1;
    #pragma unroll
    for (int mt = 0; mt < 4; mt++) {
        int r = m0 + wm * 64 + mt * 16 + (lane >> 2);
        #pragma unroll
        for (int nt = 0; nt < 4; nt++) {
            int c = n0 + wn * 32 + nt * 8 + (lane & 3) * 2;
            float b0 = bias[c], b1 = bias[c + 1];
            float2 v0 = make_float2(acc[mt][nt][0] + b0, acc[mt][nt][1] + b1);
            float2 v1 = make_float2(acc[mt][nt][2] + b0, acc[mt][nt][3] + b1);
            *(float2*)(out + (size_t)r * II + c)       = v0;
            *(float2*)(out + (size_t)(r + 8) * II + c) = v1;
        }
    }
}

// ---------------- K6: mask GEMM + epilogue (M=2048, N=B*49, K=1024) ---------
// out[b,c,n] = x[b,c,n] + sp[q] * sum_o W_w[c,o]*map[q,o],  q = b*49+n
__global__ void __launch_bounds__(256) k_mask_mma(const float* __restrict__ x,
                                                  const float* __restrict__ Ww,
                                                  float* __restrict__ out) {
    __shared__ float As[128 * 20];
    __shared__ float Bs[128 * 20];
    int n0 = blockIdx.x * 128;   // q blocks (98)
    int m0 = blockIdx.y * 128;   // c blocks (16)
    float acc[4][4][4] = {};
    gemm_core<1, II>(Ww, d_map, m0, n0, As, Bs, acc);

    int lane = threadIdx.x & 31, wid = threadIdx.x >> 5;
    int wm = wid & 1, wn = wid >> 1;
    #pragma unroll
    for (int mt = 0; mt < 4; mt++) {
        int cbase = m0 + wm * 64 + mt * 16 + (lane >> 2);
        #pragma unroll
        for (int nt = 0; nt < 4; nt++) {
            int qbase = n0 + wn * 32 + nt * 8 + (lane & 3) * 2;
            #pragma unroll
            for (int h = 0; h < 2; h++) {
                int c = cbase + h * 8;
                #pragma unroll
                for (int j = 0; j < 2; j++) {
                    int q = qbase + j;
                    int b = q / 49;
                    int n = q - b * 49;
                    size_t idx = ((size_t)b * CC + c) * NN + n;
                    out[idx] = x[idx] + d_sp[q] * acc[mt][nt][h * 2 + j];
                }
            }
        }
    }
}

// ---------------- K3: attention per batch (fp32) -----------------------------
__global__ void __launch_bounds__(256) k_attn() {
    __shared__ float th_s[4][49][17];
    __shared__ float ph_s[4][49][17];
    __shared__ float sc[49][52];

    int b = blockIdx.x;
    int tid = threadIdx.x;
    int g = tid >> 6, t = tid & 63;
    int ng = t >> 3, mg = t & 7;
    bool act = (ng < 7) && (mg < 7);

    float acc[7][7] = {};
    for (int kt = 0; kt < 16; kt++) {
        int kb = g * 256 + kt * 16;
        for (int e = t; e < 49 * 16; e += 64) {
            int r = e >> 4, kk = e & 15;
            th_s[g][r][kk] = d_tx[((size_t)b * NN + r) * II + kb + kk];
            ph_s[g][r][kk] = d_px[((size_t)b * NN + r) * II + kb + kk];
        }
        __syncthreads();
        if (act) {
            #pragma unroll
            for (int kk = 0; kk < 16; kk++) {
                float av[7], bv[7];
                #pragma unroll
                for (int i = 0; i < 7; i++) av[i] = th_s[g][ng * 7 + i][kk];
                #pragma unroll
                for (int j = 0; j < 7; j++) bv[j] = ph_s[g][mg * 7 + j][kk];
                #pragma unroll
                for (int i = 0; i < 7; i++)
                    #pragma unroll
                    for (int j = 0; j < 7; j++)
                        acc[i][j] += av[i] * bv[j];
            }
        }
        __syncthreads();
    }
    for (int gg = 0; gg < 4; gg++) {
        if (g == gg && act) {
            #pragma unroll
            for (int i = 0; i < 7; i++)
                #pragma unroll
                for (int j = 0; j < 7; j++) {
                    if (gg == 0) sc[ng * 7 + i][mg * 7 + j] = acc[i][j];
                    else         sc[ng * 7 + i][mg * 7 + j] += acc[i][j];
                }
        }
        __syncthreads();
    }
    if (tid < 49) {
        float mx = -1e30f;
        for (int m = 0; m < NN; m++) mx = fmaxf(mx, sc[tid][m]);
        float s = 0.f;
        for (int m = 0; m < NN; m++) {
            float e = expf(sc[tid][m] - mx);
            sc[tid][m] = e; s += e;
        }
        float inv = 1.f / s;
        for (int m = 0; m < NN; m++) sc[tid][m] *= inv;
    }
    __syncthreads();
    for (int op = 0; op < 4; op++) {
        int o = op * 256 + tid;
        float a2[49];
        #pragma unroll
        for (int n = 0; n < NN; n++) a2[n] = 0.f;
        for (int m = 0; m < NN; m++) {
            float gv = d_gx[((size_t)b * NN + m) * II + o];
            #pragma unroll
            for (int n = 0; n < NN; n++) a2[n] += sc[n][m] * gv;
        }
        for (int n = 0; n < NN; n++)
            d_map[((size_t)b * NN + n) * II + o] = a2[n];
    }
}

// ---------------- K4: spatial FC partials ------------------------------------
__global__ void __launch_bounds__(256) k_spart(const float* __restrict__ x,
                                               const float* __restrict__ fcw) {
    __shared__ float fc_s[49][65];
    __shared__ float x_s[16][65];
    int b0 = blockIdx.x * 16;
    int ks = blockIdx.y;
    int tid = threadIdx.x;
    int bg = tid >> 5, jg = tid & 31;
    float acc[2][2] = {};
    for (int kc = 0; kc < KPER / 64; kc++) {
        int kb = ks * KPER + kc * 64;
        for (int e = tid; e < 49 * 64; e += 256) {
            int j = e >> 6, kk = e & 63;
            fc_s[j][kk] = fcw[(size_t)j * CN + kb + kk];
        }
        for (int e = tid; e < 16 * 64; e += 256) {
            int bl = e >> 6, kk = e & 63;
            x_s[bl][kk] = x[(size_t)(b0 + bl) * CN + kb + kk];
        }
        __syncthreads();
        #pragma unroll 8
        for (int kk = 0; kk < 64; kk++) {
            float x0 = x_s[bg * 2][kk], x1 = x_s[bg * 2 + 1][kk];
            float f0 = fc_s[jg][kk];
            float f1 = (jg < 17) ? fc_s[jg + 32][kk] : 0.f;
            acc[0][0] += x0 * f0; acc[0][1] += x0 * f1;
            acc[1][0] += x1 * f0; acc[1][1] += x1 * f1;
        }
        __syncthreads();
    }
    #pragma unroll
    for (int i = 0; i < 2; i++) {
        int b = b0 + bg * 2 + i;
        d_spart[((size_t)ks * BB + b) * NN + jg] = acc[i][0];
        if (jg + 32 < NN)
            d_spart[((size_t)ks * BB + b) * NN + jg + 32] = acc[i][1];
    }
}

// ---------------- K5: reduce k-split partials + bias -------------------------
__global__ void k_sred(const float* __restrict__ fcb) {
    int b = blockIdx.x, j = threadIdx.x;
    if (j < NN) {
        float s = fcb[j];
        for (int ks = 0; ks < KSPL; ks++)
            s += d_spart[((size_t)ks * BB + b) * NN + j];
        d_sp[b * NN + j] = s;
    }
}

// ---------------------------------------------------------------------------
extern "C" void kernel_launch(void* const* d_in, const int* in_sizes, int n_in,
                              void* d_out, int out_size) {
    const float* x    = (const float*)d_in[0];
    const float* g_w  = (const float*)d_in[1];
    const float* g_b  = (const float*)d_in[2];
    const float* th_w = (const float*)d_in[3];
    const float* th_b = (const float*)d_in[4];
    const float* ph_w = (const float*)d_in[5];
    const float* ph_b = (const float*)d_in[6];
    const float* W_w  = (const float*)d_in[7];
    const float* fc_w = (const float*)d_in[8];
    const float* fc_b = (const float*)d_in[9];
    float* out = (float*)d_out;
    (void)in_sizes; (void)n_in; (void)out_size;

    float *p_gx, *p_tx, *p_px;
    cudaGetSymbolAddress((void**)&p_gx, d_gx);
    cudaGetSymbolAddress((void**)&p_tx, d_tx);
    cudaGetSymbolAddress((void**)&p_px, d_px);

    k_transpose<<<dim3(CC / 64, BB), 256>>>(x);

    dim3 pg(II / 128, (BB * NN) / 128);   // (8, 98)
    k_proj_mma<1><<<pg, 256>>>(g_w,  g_b,  p_gx);
    k_proj_mma<3><<<pg, 256>>>(th_w, th_b, p_tx);
    k_proj_mma<3><<<pg, 256>>>(ph_w, ph_b, p_px);

    k_attn<<<BB, 256>>>();

    k_spart<<<dim3(BB / 16, KSPL), 256>>>(x, fc_w);
    k_sred<<<BB, 64>>>(fc_b);

    k_mask_mma<<<dim3((BB * NN) / 128, CC / 128), 256>>>(x, W_w, out);
}

// round 3
// speedup vs baseline: 1.9556x; 1.1054x over previous
#include <cuda_runtime.h>
#include <cuda_fp16.h>

// ---------------------------------------------------------------------------
// ModulatedAttLayer  B=256, C=2048, H=W=7 (N=49), INTER=1024
//
// R3: all GEMMs on fp16x3 split tensor cores (mma.sync m16n8k16, fp32 acc).
//   v = hi + lo (fp16 each); A*B ~= Ah*Bh + Ah*Bl + Al*Bh  (error ~2^-22)
//   Splits precomputed (weights, xT, map) so the GEMM inner loop is LDS+MMA.
// ---------------------------------------------------------------------------

#define BB   256
#define CC   2048
#define NN   49
#define II   1024
#define BN   (BB*NN)      // 12544
#define CN   (CC*NN)      // 100352
#define KSPL 16
#define KPER (CN/KSPL)    // 6272

__device__ __align__(16) __half d_xh[(size_t)BN*CC];   // xT hi
__device__ __align__(16) __half d_xl[(size_t)BN*CC];   // xT lo
__device__ __align__(16) __half d_wh[(size_t)3*II*CC]; // g/theta/phi weights hi
__device__ __align__(16) __half d_wl[(size_t)3*II*CC];
__device__ __align__(16) __half d_mwh[(size_t)CC*II];  // W_w hi
__device__ __align__(16) __half d_mwl[(size_t)CC*II];
__device__ __align__(16) __half d_maph[(size_t)BN*II]; // map hi
__device__ __align__(16) __half d_mapl[(size_t)BN*II];
__device__ float d_proj[(size_t)3*BN*II];              // gx/tx/px fp32
__device__ float d_spart[(size_t)KSPL*BB*NN];
__device__ float d_sp[(size_t)BB*NN];

// ---------------- helpers ----------------------------------------------------
__device__ __forceinline__ void splith(float v, __half& h, __half& l) {
    h = __float2half_rn(v);
    l = __float2half_rn(v - __half2float(h));
}

__device__ __forceinline__ void mma16(float* d, const unsigned* a, const unsigned* b) {
    asm volatile(
        "mma.sync.aligned.m16n8k16.row.col.f32.f16.f16.f32 "
        "{%0,%1,%2,%3}, {%4,%5,%6,%7}, {%8,%9}, {%0,%1,%2,%3};\n"
        : "+f"(d[0]), "+f"(d[1]), "+f"(d[2]), "+f"(d[3])
        : "r"(a[0]), "r"(a[1]), "r"(a[2]), "r"(a[3]), "r"(b[0]), "r"(b[1]));
}

// ---------------- K0: split fp32 -> fp16 hi/lo --------------------------------
__global__ void k_split(const float* __restrict__ src, __half* __restrict__ hi,
                        __half* __restrict__ lo, int n) {
    int i = blockIdx.x * 256 + threadIdx.x;
    if (i < n) splith(src[i], hi[i], lo[i]);
}

// ---------------- K1: transpose + split x[b,c,n] -> xT hi/lo [b*49+n, c] ------
__global__ void k_transpose_split(const float* __restrict__ x) {
    __shared__ float s[64][50];
    int b = blockIdx.y, c0 = blockIdx.x * 64;
    const float* xb = x + (size_t)b * CN;
    for (int e = threadIdx.x; e < 64 * NN; e += 256) {
        int cl = e / NN, n = e - cl * NN;
        s[cl][n] = xb[(c0 + cl) * NN + n];
    }
    __syncthreads();
    for (int e = threadIdx.x; e < 64 * NN; e += 256) {
        int n = e >> 6, cl = e & 63;
        size_t o = ((size_t)b * NN + n) * CC + c0 + cl;
        splith(s[cl][n], d_xh[o], d_xl[o]);
    }
}

// ---------------- GEMM core: acc[m,n] += A[m,k]*B[n,k] (fp16x3) --------------
// CTA 128x128, kt=32, 8 warps (2m x 4n), warp tile 64x32.
// smem half tiles, row stride 40 halves (conflict-free LDS.32 fragments).
template<int K>
__device__ __forceinline__ void gemm_core(const __half* __restrict__ Ah,
                                          const __half* __restrict__ Al,
                                          const __half* __restrict__ Bh,
                                          const __half* __restrict__ Bl,
                                          int m0, int n0,
                                          __half* sAh, __half* sAl,
                                          __half* sBh, __half* sBl,
                                          float acc[4][4][4]) {
    const int tid = threadIdx.x, lane = tid & 31, wid = tid >> 5;
    const int wm = wid & 1, wn = wid >> 1;
    const int ar = lane >> 2, ak = lane & 3;

    const int idx0 = tid * 2, idx1 = tid * 2 + 1;
    const int row0 = idx0 >> 2, kc0 = (idx0 & 3) * 8;
    const int row1 = idx1 >> 2, kc1 = (idx1 & 3) * 8;

    int4 pah0 = *(const int4*)(Ah + (size_t)(m0 + row0) * K + kc0);
    int4 pah1 = *(const int4*)(Ah + (size_t)(m0 + row1) * K + kc1);
    int4 pal0 = *(const int4*)(Al + (size_t)(m0 + row0) * K + kc0);
    int4 pal1 = *(const int4*)(Al + (size_t)(m0 + row1) * K + kc1);
    int4 pbh0 = *(const int4*)(Bh + (size_t)(n0 + row0) * K + kc0);
    int4 pbh1 = *(const int4*)(Bh + (size_t)(n0 + row1) * K + kc1);
    int4 pbl0 = *(const int4*)(Bl + (size_t)(n0 + row0) * K + kc0);
    int4 pbl1 = *(const int4*)(Bl + (size_t)(n0 + row1) * K + kc1);

    for (int k0 = 0; k0 < K; k0 += 32) {
        *(int4*)&sAh[row0 * 40 + kc0] = pah0;
        *(int4*)&sAh[row1 * 40 + kc1] = pah1;
        *(int4*)&sAl[row0 * 40 + kc0] = pal0;
        *(int4*)&sAl[row1 * 40 + kc1] = pal1;
        *(int4*)&sBh[row0 * 40 + kc0] = pbh0;
        *(int4*)&sBh[row1 * 40 + kc1] = pbh1;
        *(int4*)&sBl[row0 * 40 + kc0] = pbl0;
        *(int4*)&sBl[row1 * 40 + kc1] = pbl1;
        __syncthreads();

        if (k0 + 32 < K) {
            int kn = k0 + 32;
            pah0 = *(const int4*)(Ah + (size_t)(m0 + row0) * K + kn + kc0);
            pah1 = *(const int4*)(Ah + (size_t)(m0 + row1) * K + kn + kc1);
            pal0 = *(const int4*)(Al + (size_t)(m0 + row0) * K + kn + kc0);
            pal1 = *(const int4*)(Al + (size_t)(m0 + row1) * K + kn + kc1);
            pbh0 = *(const int4*)(Bh + (size_t)(n0 + row0) * K + kn + kc0);
            pbh1 = *(const int4*)(Bh + (size_t)(n0 + row1) * K + kn + kc1);
            pbl0 = *(const int4*)(Bl + (size_t)(n0 + row0) * K + kn + kc0);
            pbl1 = *(const int4*)(Bl + (size_t)(n0 + row1) * K + kn + kc1);
        }

        #pragma unroll
        for (int ks = 0; ks < 32; ks += 16) {
            unsigned ah[4][4], al[4][4], bh[4][2], bl[4][2];
            #pragma unroll
            for (int mt = 0; mt < 4; mt++) {
                int ba = (wm * 64 + mt * 16 + ar) * 40 + ks + ak * 2;
                ah[mt][0] = *(const unsigned*)&sAh[ba];
                ah[mt][1] = *(const unsigned*)&sAh[ba + 8 * 40];
                ah[mt][2] = *(const unsigned*)&sAh[ba + 8];
                ah[mt][3] = *(const unsigned*)&sAh[ba + 8 * 40 + 8];
                al[mt][0] = *(const unsigned*)&sAl[ba];
                al[mt][1] = *(const unsigned*)&sAl[ba + 8 * 40];
                al[mt][2] = *(const unsigned*)&sAl[ba + 8];
                al[mt][3] = *(const unsigned*)&sAl[ba + 8 * 40 + 8];
            }
            #pragma unroll
            for (int nt = 0; nt < 4; nt++) {
                int bb = (wn * 32 + nt * 8 + ar) * 40 + ks + ak * 2;
                bh[nt][0] = *(const unsigned*)&sBh[bb];
                bh[nt][1] = *(const unsigned*)&sBh[bb + 8];
                bl[nt][0] = *(const unsigned*)&sBl[bb];
                bl[nt][1] = *(const unsigned*)&sBl[bb + 8];
            }
            #pragma unroll
            for (int mt = 0; mt < 4; mt++)
                #pragma unroll
                for (int nt = 0; nt < 4; nt++) {
                    mma16(acc[mt][nt], al[mt], bh[nt]);
                    mma16(acc[mt][nt], ah[mt], bl[nt]);
                    mma16(acc[mt][nt], ah[mt], bh[nt]);
                }
        }
        __syncthreads();
    }
}

// ---------------- K2: 3 projections fused (M=12544, N=1024, K=2048) ----------
__global__ void __launch_bounds__(256) k_proj3(const float* __restrict__ g_b,
                                               const float* __restrict__ th_b,
                                               const float* __restrict__ ph_b) {
    __shared__ __align__(16) __half sAh[128 * 40], sAl[128 * 40];
    __shared__ __align__(16) __half sBh[128 * 40], sBl[128 * 40];
    int n0 = blockIdx.x * 128, m0 = blockIdx.y * 128, z = blockIdx.z;
    const __half* wh = d_wh + (size_t)z * II * CC;
    const __half* wl = d_wl + (size_t)z * II * CC;
    const float* bias = (z == 0) ? g_b : (z == 1) ? th_b : ph_b;
    float* out = d_proj + (size_t)z * BN * II;

    float acc[4][4][4] = {};
    gemm_core<CC>(d_xh, d_xl, wh, wl, m0, n0, sAh, sAl, sBh, sBl, acc);

    int lane = threadIdx.x & 31, wid = threadIdx.x >> 5;
    int wm = wid & 1, wn = wid >> 1;
    #pragma unroll
    for (int mt = 0; mt < 4; mt++) {
        int r = m0 + wm * 64 + mt * 16 + (lane >> 2);
        #pragma unroll
        for (int nt = 0; nt < 4; nt++) {
            int c = n0 + wn * 32 + nt * 8 + (lane & 3) * 2;
            float b0 = bias[c], b1 = bias[c + 1];
            *(float2*)(out + (size_t)r * II + c) =
                make_float2(acc[mt][nt][0] + b0, acc[mt][nt][1] + b1);
            *(float2*)(out + (size_t)(r + 8) * II + c) =
                make_float2(acc[mt][nt][2] + b0, acc[mt][nt][3] + b1);
        }
    }
}

// ---------------- K6: mask GEMM + epilogue (M=2048, N=B*49, K=1024) ----------
__global__ void __launch_bounds__(256) k_mask_mma(const float* __restrict__ x,
                                                  float* __restrict__ out) {
    __shared__ __align__(16) __half sAh[128 * 40], sAl[128 * 40];
    __shared__ __align__(16) __half sBh[128 * 40], sBl[128 * 40];
    int n0 = blockIdx.x * 128;   // q blocks (98)
    int m0 = blockIdx.y * 128;   // c blocks (16)
    float acc[4][4][4] = {};
    gemm_core<II>(d_mwh, d_mwl, d_maph, d_mapl, m0, n0, sAh, sAl, sBh, sBl, acc);

    int lane = threadIdx.x & 31, wid = threadIdx.x >> 5;
    int wm = wid & 1, wn = wid >> 1;
    #pragma unroll
    for (int mt = 0; mt < 4; mt++) {
        int cbase = m0 + wm * 64 + mt * 16 + (lane >> 2);
        #pragma unroll
        for (int nt = 0; nt < 4; nt++) {
            int qbase = n0 + wn * 32 + nt * 8 + (lane & 3) * 2;
            #pragma unroll
            for (int h = 0; h < 2; h++) {
                int c = cbase + h * 8;
                #pragma unroll
                for (int j = 0; j < 2; j++) {
                    int q = qbase + j;
                    int b = q / 49;
                    int n = q - b * 49;
                    size_t idx = ((size_t)b * CC + c) * NN + n;
                    out[idx] = x[idx] + d_sp[q] * acc[mt][nt][h * 2 + j];
                }
            }
        }
    }
}

// ---------------- K3: attention per batch (fp32), writes map hi/lo -----------
__global__ void __launch_bounds__(256) k_attn() {
    __shared__ float th_s[4][49][17];
    __shared__ float ph_s[4][49][17];
    __shared__ float sc[49][52];

    const float* gx = d_proj;
    const float* tx = d_proj + (size_t)BN * II;
    const float* px = d_proj + (size_t)2 * BN * II;

    int b = blockIdx.x;
    int tid = threadIdx.x;
    int g = tid >> 6, t = tid & 63;
    int ng = t >> 3, mg = t & 7;
    bool act = (ng < 7) && (mg < 7);

    float acc[7][7] = {};
    for (int kt = 0; kt < 16; kt++) {
        int kb = g * 256 + kt * 16;
        for (int e = t; e < 49 * 16; e += 64) {
            int r = e >> 4, kk = e & 15;
            th_s[g][r][kk] = tx[((size_t)b * NN + r) * II + kb + kk];
            ph_s[g][r][kk] = px[((size_t)b * NN + r) * II + kb + kk];
        }
        __syncthreads();
        if (act) {
            #pragma unroll
            for (int kk = 0; kk < 16; kk++) {
                float av[7], bv[7];
                #pragma unroll
                for (int i = 0; i < 7; i++) av[i] = th_s[g][ng * 7 + i][kk];
                #pragma unroll
                for (int j = 0; j < 7; j++) bv[j] = ph_s[g][mg * 7 + j][kk];
                #pragma unroll
                for (int i = 0; i < 7; i++)
                    #pragma unroll
                    for (int j = 0; j < 7; j++)
                        acc[i][j] += av[i] * bv[j];
            }
        }
        __syncthreads();
    }
    for (int gg = 0; gg < 4; gg++) {
        if (g == gg && act) {
            #pragma unroll
            for (int i = 0; i < 7; i++)
                #pragma unroll
                for (int j = 0; j < 7; j++) {
                    if (gg == 0) sc[ng * 7 + i][mg * 7 + j] = acc[i][j];
                    else         sc[ng * 7 + i][mg * 7 + j] += acc[i][j];
                }
        }
        __syncthreads();
    }
    if (tid < 49) {
        float mx = -1e30f;
        for (int m = 0; m < NN; m++) mx = fmaxf(mx, sc[tid][m]);
        float s = 0.f;
        for (int m = 0; m < NN; m++) {
            float e = expf(sc[tid][m] - mx);
            sc[tid][m] = e; s += e;
        }
        float inv = 1.f / s;
        for (int m = 0; m < NN; m++) sc[tid][m] *= inv;
    }
    __syncthreads();
    for (int op = 0; op < 4; op++) {
        int o = op * 256 + tid;
        float a2[49];
        #pragma unroll
        for (int n = 0; n < NN; n++) a2[n] = 0.f;
        for (int m = 0; m < NN; m++) {
            float gv = gx[((size_t)b * NN + m) * II + o];
            #pragma unroll
            for (int n = 0; n < NN; n++) a2[n] += sc[n][m] * gv;
        }
        for (int n = 0; n < NN; n++) {
            size_t oo = ((size_t)b * NN + n) * II + o;
            splith(a2[n], d_maph[oo], d_mapl[oo]);
        }
    }
}

// ---------------- K4: spatial FC partials ------------------------------------
__global__ void __launch_bounds__(256) k_spart(const float* __restrict__ x,
                                               const float* __restrict__ fcw) {
    __shared__ float fc_s[49][65];
    __shared__ float x_s[16][65];
    int b0 = blockIdx.x * 16;
    int ks = blockIdx.y;
    int tid = threadIdx.x;
    int bg = tid >> 5, jg = tid & 31;
    float acc[2][2] = {};
    for (int kc = 0; kc < KPER / 64; kc++) {
        int kb = ks * KPER + kc * 64;
        for (int e = tid; e < 49 * 64; e += 256) {
            int j = e >> 6, kk = e & 63;
            fc_s[j][kk] = fcw[(size_t)j * CN + kb + kk];
        }
        for (int e = tid; e < 16 * 64; e += 256) {
            int bl = e >> 6, kk = e & 63;
            x_s[bl][kk] = x[(size_t)(b0 + bl) * CN + kb + kk];
        }
        __syncthreads();
        #pragma unroll 8
        for (int kk = 0; kk < 64; kk++) {
            float x0 = x_s[bg * 2][kk], x1 = x_s[bg * 2 + 1][kk];
            float f0 = fc_s[jg][kk];
            float f1 = (jg < 17) ? fc_s[jg + 32][kk] : 0.f;
            acc[0][0] += x0 * f0; acc[0][1] += x0 * f1;
            acc[1][0] += x1 * f0; acc[1][1] += x1 * f1;
        }
        __syncthreads();
    }
    #pragma unroll
    for (int i = 0; i < 2; i++) {
        int b = b0 + bg * 2 + i;
        d_spart[((size_t)ks * BB + b) * NN + jg] = acc[i][0];
        if (jg + 32 < NN)
            d_spart[((size_t)ks * BB + b) * NN + jg + 32] = acc[i][1];
    }
}

// ---------------- K5: reduce k-split partials + bias -------------------------
__global__ void k_sred(const float* __restrict__ fcb) {
    int b = blockIdx.x, j = threadIdx.x;
    if (j < NN) {
        float s = fcb[j];
        for (int ks = 0; ks < KSPL; ks++)
            s += d_spart[((size_t)ks * BB + b) * NN + j];
        d_sp[b * NN + j] = s;
    }
}

// ---------------------------------------------------------------------------
extern "C" void kernel_launch(void* const* d_in, const int* in_sizes, int n_in,
                              void* d_out, int out_size) {
    const float* x    = (const float*)d_in[0];
    const float* g_w  = (const float*)d_in[1];
    const float* g_b  = (const float*)d_in[2];
    const float* th_w = (const float*)d_in[3];
    const float* th_b = (const float*)d_in[4];
    const float* ph_w = (const float*)d_in[5];
    const float* ph_b = (const float*)d_in[6];
    const float* W_w  = (const float*)d_in[7];
    const float* fc_w = (const float*)d_in[8];
    const float* fc_b = (const float*)d_in[9];
    float* out = (float*)d_out;
    (void)in_sizes; (void)n_in; (void)out_size;

    __half *p_wh, *p_wl, *p_mwh, *p_mwl;
    cudaGetSymbolAddress((void**)&p_wh,  d_wh);
    cudaGetSymbolAddress((void**)&p_wl,  d_wl);
    cudaGetSymbolAddress((void**)&p_mwh, d_mwh);
    cudaGetSymbolAddress((void**)&p_mwl, d_mwl);

    const int WSZ = II * CC;  // 2M
    k_split<<<(WSZ + 255) / 256, 256>>>(g_w,  p_wh,            p_wl,            WSZ);
    k_split<<<(WSZ + 255) / 256, 256>>>(th_w, p_wh + WSZ,      p_wl + WSZ,      WSZ);
    k_split<<<(WSZ + 255) / 256, 256>>>(ph_w, p_wh + 2 * WSZ,  p_wl + 2 * WSZ,  WSZ);
    k_split<<<(WSZ + 255) / 256, 256>>>(W_w,  p_mwh,           p_mwl,           WSZ);

    k_transpose_split<<<dim3(CC / 64, BB), 256>>>(x);

    k_proj3<<<dim3(II / 128, BN / 128, 3), 256>>>(g_b, th_b, ph_b);

    k_attn<<<BB, 256>>>();

    k_spart<<<dim3(BB / 16, KSPL), 256>>>(x, fc_w);
    k_sred<<<BB, 64>>>(fc_b);

    k_mask_mma<<<dim3(BN / 128, CC / 128), 256>>>(x, out);
}

// round 4
// speedup vs baseline: 2.6432x; 1.3516x over previous
#include <cuda_runtime.h>
#include <cuda_fp16.h>

// ---------------------------------------------------------------------------
// ModulatedAttLayer  B=256, C=2048, H=W=7 (N=49), INTER=1024
//
// R4: precision-tiered fp16 tensor-core GEMMs + cp.async double buffering.
//   theta/phi projections : fp16x3 split (softmax-critical, ~2^-22 error)
//   g projection, mask    : single fp16 (linear path, tolerance analysis ok)
// ---------------------------------------------------------------------------

#define BB   256
#define CC   2048
#define NN   49
#define II   1024
#define BN   (BB*NN)      // 12544
#define CN   (CC*NN)      // 100352
#define KSPL 16
#define KPER (CN/KSPL)    // 6272

__device__ __align__(16) __half d_xh[(size_t)BN*CC];   // xT hi
__device__ __align__(16) __half d_xl[(size_t)BN*CC];   // xT lo
__device__ __align__(16) __half d_wh[(size_t)3*II*CC]; // g/theta/phi weights hi
__device__ __align__(16) __half d_wl[(size_t)3*II*CC]; // lo (theta/phi only used)
__device__ __align__(16) __half d_mwh[(size_t)CC*II];  // W_w hi
__device__ __align__(16) __half d_maph[(size_t)BN*II]; // map hi
__device__ float d_proj[(size_t)3*BN*II];              // gx/tx/px fp32
__device__ float d_spart[(size_t)KSPL*BB*NN];
__device__ float d_sp[(size_t)BB*NN];

// ---------------- helpers ----------------------------------------------------
__device__ __forceinline__ void splith(float v, __half& h, __half& l) {
    h = __float2half_rn(v);
    l = __float2half_rn(v - __half2float(h));
}

__device__ __forceinline__ void mma16(float* d, const unsigned* a, const unsigned* b) {
    asm volatile(
        "mma.sync.aligned.m16n8k16.row.col.f32.f16.f16.f32 "
        "{%0,%1,%2,%3}, {%4,%5,%6,%7}, {%8,%9}, {%0,%1,%2,%3};\n"
        : "+f"(d[0]), "+f"(d[1]), "+f"(d[2]), "+f"(d[3])
        : "r"(a[0]), "r"(a[1]), "r"(a[2]), "r"(a[3]), "r"(b[0]), "r"(b[1]));
}

__device__ __forceinline__ void cpa16(__half* smem, const __half* g) {
    unsigned s = (unsigned)__cvta_generic_to_shared(smem);
    asm volatile("cp.async.cg.shared.global [%0], [%1], 16;\n" :: "r"(s), "l"(g));
}
__device__ __forceinline__ void cpcommit() { asm volatile("cp.async.commit_group;\n"); }
__device__ __forceinline__ void cpwait1()  { asm volatile("cp.async.wait_group 1;\n" ::: "memory"); }
__device__ __forceinline__ void cpwait0()  { asm volatile("cp.async.wait_group 0;\n" ::: "memory"); }

// ---------------- K0: split fp32 -> fp16 hi/lo --------------------------------
__global__ void k_split(const float* __restrict__ src, __half* __restrict__ hi,
                        __half* __restrict__ lo, int n) {
    int i = blockIdx.x * 256 + threadIdx.x;
    if (i < n) splith(src[i], hi[i], lo[i]);
}
__global__ void k_split1(const float* __restrict__ src, __half* __restrict__ hi, int n) {
    int i = blockIdx.x * 256 + threadIdx.x;
    if (i < n) hi[i] = __float2half_rn(src[i]);
}

// ---------------- K1: transpose + split x[b,c,n] -> xT hi/lo [b*49+n, c] ------
__global__ void k_transpose_split(const float* __restrict__ x) {
    __shared__ float s[64][50];
    int b = blockIdx.y, c0 = blockIdx.x * 64;
    const float* xb = x + (size_t)b * CN;
    for (int e = threadIdx.x; e < 64 * NN; e += 256) {
        int cl = e / NN, n = e - cl * NN;
        s[cl][n] = xb[(c0 + cl) * NN + n];
    }
    __syncthreads();
    for (int e = threadIdx.x; e < 64 * NN; e += 256) {
        int n = e >> 6, cl = e & 63;
        size_t o = ((size_t)b * NN + n) * CC + c0 + cl;
        splith(s[cl][n], d_xh[o], d_xl[o]);
    }
}

// ---------------- GEMM core: acc[m,n] += A[m,k]*B[n,k] ------------------------
// CTA 128x128, kt=16, 8 warps (2m x 4n), warp tile 64x32.
// cp.async double-buffered smem; row stride 24 halves (conflict-free LDS.32).
// Tile order per stage: [Ah, Bh, (Al, Bl if NSPLIT==3)]
template<int NSPLIT, int K>
__device__ __forceinline__ void gemm_core(
    const __half* __restrict__ Ah, const __half* __restrict__ Al,
    const __half* __restrict__ Bh, const __half* __restrict__ Bl,
    int m0, int n0, __half* sm, float acc[4][4][4])
{
    constexpr int NT  = (NSPLIT == 3) ? 4 : 2;
    constexpr int TSZ = 128 * 24;
    const int tid  = threadIdx.x, lane = tid & 31, wid = tid >> 5;
    const int wm = wid & 1, wn = wid >> 1;
    const int ar = lane >> 2, ak = lane & 3;
    const int row = tid >> 1, seg = (tid & 1) * 8;
    const int dst = row * 24 + seg;

    const __half* Agr = Ah + (size_t)(m0 + row) * K + seg;
    const __half* Bgr = Bh + (size_t)(n0 + row) * K + seg;
    const __half* Alr = (NSPLIT == 3) ? Al + (size_t)(m0 + row) * K + seg : nullptr;
    const __half* Blr = (NSPLIT == 3) ? Bl + (size_t)(n0 + row) * K + seg : nullptr;

    // prologue: stage 0
    {
        __half* bse = sm;
        cpa16(bse + dst, Agr);
        cpa16(bse + TSZ + dst, Bgr);
        if (NSPLIT == 3) {
            cpa16(bse + 2 * TSZ + dst, Alr);
            cpa16(bse + 3 * TSZ + dst, Blr);
        }
        cpcommit();
    }

    constexpr int T = K / 16;
    for (int t = 0; t < T; t++) {
        if (t + 1 < T) {
            __half* bse = sm + ((t + 1) & 1) * NT * TSZ;
            int kof = (t + 1) * 16;
            cpa16(bse + dst, Agr + kof);
            cpa16(bse + TSZ + dst, Bgr + kof);
            if (NSPLIT == 3) {
                cpa16(bse + 2 * TSZ + dst, Alr + kof);
                cpa16(bse + 3 * TSZ + dst, Blr + kof);
            }
            cpcommit();
            cpwait1();
        } else {
            cpwait0();
        }
        __syncthreads();

        const __half* bse = sm + (t & 1) * NT * TSZ;
        const __half* tAh = bse;
        const __half* tBh = bse + TSZ;
        const __half* tAl = bse + 2 * TSZ;
        const __half* tBl = bse + 3 * TSZ;

        unsigned ah[4][4], bh[4][2], al[4][4], bl[4][2];
        #pragma unroll
        for (int mt = 0; mt < 4; mt++) {
            int ia = (wm * 64 + mt * 16 + ar) * 24 + ak * 2;
            ah[mt][0] = *(const unsigned*)&tAh[ia];
            ah[mt][1] = *(const unsigned*)&tAh[ia + 8 * 24];
            ah[mt][2] = *(const unsigned*)&tAh[ia + 8];
            ah[mt][3] = *(const unsigned*)&tAh[ia + 8 * 24 + 8];
            if (NSPLIT == 3) {
                al[mt][0] = *(const unsigned*)&tAl[ia];
                al[mt][1] = *(const unsigned*)&tAl[ia + 8 * 24];
                al[mt][2] = *(const unsigned*)&tAl[ia + 8];
                al[mt][3] = *(const unsigned*)&tAl[ia + 8 * 24 + 8];
            }
        }
        #pragma unroll
        for (int nt = 0; nt < 4; nt++) {
            int ib = (wn * 32 + nt * 8 + ar) * 24 + ak * 2;
            bh[nt][0] = *(const unsigned*)&tBh[ib];
            bh[nt][1] = *(const unsigned*)&tBh[ib + 8];
            if (NSPLIT == 3) {
                bl[nt][0] = *(const unsigned*)&tBl[ib];
                bl[nt][1] = *(const unsigned*)&tBl[ib + 8];
            }
        }
        #pragma unroll
        for (int mt = 0; mt < 4; mt++)
            #pragma unroll
            for (int nt = 0; nt < 4; nt++) {
                if (NSPLIT == 3) {
                    mma16(acc[mt][nt], al[mt], bh[nt]);
                    mma16(acc[mt][nt], ah[mt], bl[nt]);
                }
                mma16(acc[mt][nt], ah[mt], bh[nt]);
            }
        __syncthreads();
    }
}

// ---------------- K2: projection (M=12544, N=1024, K=2048) --------------------
template<int NSPLIT>
__global__ void __launch_bounds__(256) k_proj_mma(const __half* __restrict__ wh,
                                                  const __half* __restrict__ wl,
                                                  const float* __restrict__ bias,
                                                  float* __restrict__ out) {
    __shared__ __align__(16) __half sm[2 * ((NSPLIT == 3) ? 4 : 2) * 128 * 24];
    int n0 = blockIdx.x * 128, m0 = blockIdx.y * 128;
    float acc[4][4][4] = {};
    gemm_core<NSPLIT, CC>(d_xh, d_xl, wh, wl, m0, n0, sm, acc);

    int lane = threadIdx.x & 31, wid = threadIdx.x >> 5;
    int wm = wid & 1, wn = wid >> 1;
    #pragma unroll
    for (int mt = 0; mt < 4; mt++) {
        int r = m0 + wm * 64 + mt * 16 + (lane >> 2);
        #pragma unroll
        for (int nt = 0; nt < 4; nt++) {
            int c = n0 + wn * 32 + nt * 8 + (lane & 3) * 2;
            float b0 = bias[c], b1 = bias[c + 1];
            *(float2*)(out + (size_t)r * II + c) =
                make_float2(acc[mt][nt][0] + b0, acc[mt][nt][1] + b1);
            *(float2*)(out + (size_t)(r + 8) * II + c) =
                make_float2(acc[mt][nt][2] + b0, acc[mt][nt][3] + b1);
        }
    }
}

// ---------------- K6: mask GEMM + epilogue (M=2048, N=B*49, K=1024) -----------
__global__ void __launch_bounds__(256) k_mask_mma(const float* __restrict__ x,
                                                  float* __restrict__ out) {
    __shared__ __align__(16) __half sm[2 * 2 * 128 * 24];
    int n0 = blockIdx.x * 128;   // q blocks (98)
    int m0 = blockIdx.y * 128;   // c blocks (16)
    float acc[4][4][4] = {};
    gemm_core<1, II>(d_mwh, nullptr, d_maph, nullptr, m0, n0, sm, acc);

    int lane = threadIdx.x & 31, wid = threadIdx.x >> 5;
    int wm = wid & 1, wn = wid >> 1;
    #pragma unroll
    for (int mt = 0; mt < 4; mt++) {
        int cbase = m0 + wm * 64 + mt * 16 + (lane >> 2);
        #pragma unroll
        for (int nt = 0; nt < 4; nt++) {
            int qbase = n0 + wn * 32 + nt * 8 + (lane & 3) * 2;
            #pragma unroll
            for (int h = 0; h < 2; h++) {
                int c = cbase + h * 8;
                #pragma unroll
                for (int j = 0; j < 2; j++) {
                    int q = qbase + j;
                    int b = q / 49;
                    int n = q - b * 49;
                    size_t idx = ((size_t)b * CC + c) * NN + n;
                    out[idx] = x[idx] + d_sp[q] * acc[mt][nt][h * 2 + j];
                }
            }
        }
    }
}

// ---------------- K3: attention per batch (fp32), writes map hi ---------------
__global__ void __launch_bounds__(256) k_attn() {
    __shared__ float th_s[4][49][17];
    __shared__ float ph_s[4][49][17];
    __shared__ float sc[49][52];

    const float* gx = d_proj;
    const float* tx = d_proj + (size_t)BN * II;
    const float* px = d_proj + (size_t)2 * BN * II;

    int b = blockIdx.x;
    int tid = threadIdx.x;
    int g = tid >> 6, t = tid & 63;
    int ng = t >> 3, mg = t & 7;
    bool act = (ng < 7) && (mg < 7);

    float acc[7][7] = {};
    for (int kt = 0; kt < 16; kt++) {
        int kb = g * 256 + kt * 16;
        for (int e = t; e < 49 * 16; e += 64) {
            int r = e >> 4, kk = e & 15;
            th_s[g][r][kk] = tx[((size_t)b * NN + r) * II + kb + kk];
            ph_s[g][r][kk] = px[((size_t)b * NN + r) * II + kb + kk];
        }
        __syncthreads();
        if (act) {
            #pragma unroll
            for (int kk = 0; kk < 16; kk++) {
                float av[7], bv[7];
                #pragma unroll
                for (int i = 0; i < 7; i++) av[i] = th_s[g][ng * 7 + i][kk];
                #pragma unroll
                for (int j = 0; j < 7; j++) bv[j] = ph_s[g][mg * 7 + j][kk];
                #pragma unroll
                for (int i = 0; i < 7; i++)
                    #pragma unroll
                    for (int j = 0; j < 7; j++)
                        acc[i][j] += av[i] * bv[j];
            }
        }
        __syncthreads();
    }
    for (int gg = 0; gg < 4; gg++) {
        if (g == gg && act) {
            #pragma unroll
            for (int i = 0; i < 7; i++)
                #pragma unroll
                for (int j = 0; j < 7; j++) {
                    if (gg == 0) sc[ng * 7 + i][mg * 7 + j] = acc[i][j];
                    else         sc[ng * 7 + i][mg * 7 + j] += acc[i][j];
                }
        }
        __syncthreads();
    }
    if (tid < 49) {
        float mx = -1e30f;
        for (int m = 0; m < NN; m++) mx = fmaxf(mx, sc[tid][m]);
        float s = 0.f;
        for (int m = 0; m < NN; m++) {
            float e = expf(sc[tid][m] - mx);
            sc[tid][m] = e; s += e;
        }
        float inv = 1.f / s;
        for (int m = 0; m < NN; m++) sc[tid][m] *= inv;
    }
    __syncthreads();
    for (int op = 0; op < 4; op++) {
        int o = op * 256 + tid;
        float a2[49];
        #pragma unroll
        for (int n = 0; n < NN; n++) a2[n] = 0.f;
        for (int m = 0; m < NN; m++) {
            float gv = gx[((size_t)b * NN + m) * II + o];
            #pragma unroll
            for (int n = 0; n < NN; n++) a2[n] += sc[n][m] * gv;
        }
        for (int n = 0; n < NN; n++)
            d_maph[((size_t)b * NN + n) * II + o] = __float2half_rn(a2[n]);
    }
}

// ---------------- K4: spatial FC partials ------------------------------------
__global__ void __launch_bounds__(256) k_spart(const float* __restrict__ x,
                                               const float* __restrict__ fcw) {
    __shared__ float fc_s[49][65];
    __shared__ float x_s[16][65];
    int b0 = blockIdx.x * 16;
    int ks = blockIdx.y;
    int tid = threadIdx.x;
    int bg = tid >> 5, jg = tid & 31;
    float acc[2][2] = {};
    for (int kc = 0; kc < KPER / 64; kc++) {
        int kb = ks * KPER + kc * 64;
        for (int e = tid; e < 49 * 64; e += 256) {
            int j = e >> 6, kk = e & 63;
            fc_s[j][kk] = fcw[(size_t)j * CN + kb + kk];
        }
        for (int e = tid; e < 16 * 64; e += 256) {
            int bl = e >> 6, kk = e & 63;
            x_s[bl][kk] = x[(size_t)(b0 + bl) * CN + kb + kk];
        }
        __syncthreads();
        #pragma unroll 8
        for (int kk = 0; kk < 64; kk++) {
            float x0 = x_s[bg * 2][kk], x1 = x_s[bg * 2 + 1][kk];
            float f0 = fc_s[jg][kk];
            float f1 = (jg < 17) ? fc_s[jg + 32][kk] : 0.f;
            acc[0][0] += x0 * f0; acc[0][1] += x0 * f1;
            acc[1][0] += x1 * f0; acc[1][1] += x1 * f1;
        }
        __syncthreads();
    }
    #pragma unroll
    for (int i = 0; i < 2; i++) {
        int b = b0 + bg * 2 + i;
        d_spart[((size_t)ks * BB + b) * NN + jg] = acc[i][0];
        if (jg + 32 < NN)
            d_spart[((size_t)ks * BB + b) * NN + jg + 32] = acc[i][1];
    }
}

// ---------------- K5: reduce k-split partials + bias --------------------------
__global__ void k_sred(const float* __restrict__ fcb) {
    int b = blockIdx.x, j = threadIdx.x;
    if (j < NN) {
        float s = fcb[j];
        for (int ks = 0; ks < KSPL; ks++)
            s += d_spart[((size_t)ks * BB + b) * NN + j];
        d_sp[b * NN + j] = s;
    }
}

// ---------------------------------------------------------------------------
extern "C" void kernel_launch(void* const* d_in, const int* in_sizes, int n_in,
                              void* d_out, int out_size) {
    const float* x    = (const float*)d_in[0];
    const float* g_w  = (const float*)d_in[1];
    const float* g_b  = (const float*)d_in[2];
    const float* th_w = (const float*)d_in[3];
    const float* th_b = (const float*)d_in[4];
    const float* ph_w = (const float*)d_in[5];
    const float* ph_b = (const float*)d_in[6];
    const float* W_w  = (const float*)d_in[7];
    const float* fc_w = (const float*)d_in[8];
    const float* fc_b = (const float*)d_in[9];
    float* out = (float*)d_out;
    (void)in_sizes; (void)n_in; (void)out_size;

    __half *p_wh, *p_wl, *p_mwh;
    float* p_proj;
    cudaGetSymbolAddress((void**)&p_wh,  d_wh);
    cudaGetSymbolAddress((void**)&p_wl,  d_wl);
    cudaGetSymbolAddress((void**)&p_mwh, d_mwh);
    cudaGetSymbolAddress((void**)&p_proj, d_proj);

    const int WSZ = II * CC;  // 2M
    k_split1<<<(WSZ + 255) / 256, 256>>>(g_w,  p_wh, WSZ);
    k_split <<<(WSZ + 255) / 256, 256>>>(th_w, p_wh + WSZ,     p_wl + WSZ,     WSZ);
    k_split <<<(WSZ + 255) / 256, 256>>>(ph_w, p_wh + 2 * WSZ, p_wl + 2 * WSZ, WSZ);
    k_split1<<<(WSZ + 255) / 256, 256>>>(W_w,  p_mwh, WSZ);

    k_transpose_split<<<dim3(CC / 64, BB), 256>>>(x);

    dim3 pg(II / 128, BN / 128);   // (8, 98)
    k_proj_mma<1><<<pg, 256>>>(p_wh,           nullptr,        g_b,  p_proj);
    k_proj_mma<3><<<pg, 256>>>(p_wh + WSZ,     p_wl + WSZ,     th_b, p_proj + (size_t)BN * II);
    k_proj_mma<3><<<pg, 256>>>(p_wh + 2 * WSZ, p_wl + 2 * WSZ, ph_b, p_proj + (size_t)2 * BN * II);

    k_attn<<<BB, 256>>>();

    k_spart<<<dim3(BB / 16, KSPL), 256>>>(x, fc_w);
    k_sred<<<BB, 64>>>(fc_b);

    k_mask_mma<<<dim3(BN / 128, CC / 128), 256>>>(x, out);
}

// round 5
// speedup vs baseline: 3.0530x; 1.1550x over previous
#include <cuda_runtime.h>
#include <cuda_fp16.h>

// ---------------------------------------------------------------------------
// ModulatedAttLayer  B=256, C=2048, H=W=7 (N=49), INTER=1024
//
// R5: fp16 tensor-core GEMMs with ldmatrix + swizzled smem + multi-stage
//     cp.async (1 barrier per k-step).
//   theta/phi projections : fp16x3 split (softmax-critical, ~2^-22 error)
//   g projection, mask    : single fp16
// ---------------------------------------------------------------------------

#define BB   256
#define CC   2048
#define NN   49
#define II   1024
#define BN   (BB*NN)      // 12544
#define CN   (CC*NN)      // 100352
#define KSPL 16
#define KPER (CN/KSPL)    // 6272

__device__ __align__(16) __half d_xh[(size_t)BN*CC];   // xT hi
__device__ __align__(16) __half d_xl[(size_t)BN*CC];   // xT lo
__device__ __align__(16) __half d_wh[(size_t)3*II*CC]; // g/theta/phi weights hi
__device__ __align__(16) __half d_wl[(size_t)3*II*CC]; // lo (theta/phi used)
__device__ __align__(16) __half d_mwh[(size_t)CC*II];  // W_w hi
__device__ __align__(16) __half d_maph[(size_t)BN*II]; // map hi
__device__ float d_proj[(size_t)3*BN*II];              // gx/tx/px fp32
__device__ float d_spart[(size_t)KSPL*BB*NN];
__device__ float d_sp[(size_t)BB*NN];

// ---------------- helpers ----------------------------------------------------
__device__ __forceinline__ void splith(float v, __half& h, __half& l) {
    h = __float2half_rn(v);
    l = __float2half_rn(v - __half2float(h));
}

__device__ __forceinline__ void mma16(float* d, const unsigned* a, const unsigned* b) {
    asm volatile(
        "mma.sync.aligned.m16n8k16.row.col.f32.f16.f16.f32 "
        "{%0,%1,%2,%3}, {%4,%5,%6,%7}, {%8,%9}, {%0,%1,%2,%3};\n"
        : "+f"(d[0]), "+f"(d[1]), "+f"(d[2]), "+f"(d[3])
        : "r"(a[0]), "r"(a[1]), "r"(a[2]), "r"(a[3]), "r"(b[0]), "r"(b[1]));
}

__device__ __forceinline__ void cpa16s(unsigned s, const __half* g) {
    asm volatile("cp.async.cg.shared.global [%0], [%1], 16;\n" :: "r"(s), "l"(g));
}
__device__ __forceinline__ void cpcommit() { asm volatile("cp.async.commit_group;\n"); }
template<int N>
__device__ __forceinline__ void cpwaitN() {
    asm volatile("cp.async.wait_group %0;\n" :: "n"(N) : "memory");
}
__device__ __forceinline__ void ldsm4(unsigned& r0, unsigned& r1, unsigned& r2,
                                      unsigned& r3, unsigned addr) {
    asm volatile("ldmatrix.sync.aligned.m8n8.x4.shared.b16 {%0,%1,%2,%3}, [%4];"
                 : "=r"(r0), "=r"(r1), "=r"(r2), "=r"(r3) : "r"(addr));
}

// ---------------- K0: split fp32 -> fp16 hi/lo --------------------------------
__global__ void k_split(const float* __restrict__ src, __half* __restrict__ hi,
                        __half* __restrict__ lo, int n) {
    int i = blockIdx.x * 256 + threadIdx.x;
    if (i < n) splith(src[i], hi[i], lo[i]);
}
__global__ void k_split1(const float* __restrict__ src, __half* __restrict__ hi, int n) {
    int i = blockIdx.x * 256 + threadIdx.x;
    if (i < n) hi[i] = __float2half_rn(src[i]);
}

// ---------------- K1: transpose + split x[b,c,n] -> xT hi/lo [b*49+n, c] ------
__global__ void k_transpose_split(const float* __restrict__ x) {
    __shared__ float s[64][50];
    int b = blockIdx.y, c0 = blockIdx.x * 64;
    const float* xb = x + (size_t)b * CN;
    for (int e = threadIdx.x; e < 64 * NN; e += 256) {
        int cl = e / NN, n = e - cl * NN;
        s[cl][n] = xb[(c0 + cl) * NN + n];
    }
    __syncthreads();
    for (int e = threadIdx.x; e < 64 * NN; e += 256) {
        int n = e >> 6, cl = e & 63;
        size_t o = ((size_t)b * NN + n) * CC + c0 + cl;
        splith(s[cl][n], d_xh[o], d_xl[o]);
    }
}

// ---------------- GEMM core: acc[m,n] += A[m,k]*B[n,k] ------------------------
// CTA 128x128, k-step 32, 8 warps (2m x 4n), warp tile 64x32.
// smem tile: 128 rows x 32 halves (64B rows), 16B chunks XOR-swizzled by
// chunk' = chunk ^ ((row>>1)&3)  -> LDSM phases conflict-free.
// Multi-stage cp.async, ONE __syncthreads per k-step.
template<int NSPLIT, int STAGES, int K>
__device__ __forceinline__ void gemm_core(
    const __half* __restrict__ Ah, const __half* __restrict__ Al,
    const __half* __restrict__ Bh, const __half* __restrict__ Bl,
    int m0, int n0, unsigned sb, float acc[4][4][4])
{
    constexpr int NT   = (NSPLIT == 3) ? 4 : 2;
    constexpr int TILB = 128 * 32 * 2;   // tile bytes (8KB)
    constexpr int STB  = NT * TILB;      // stage bytes
    constexpr int T    = K / 32;
    const int tid = threadIdx.x, lane = tid & 31, wid = tid >> 5;
    const int wm = wid & 1, wn = wid >> 1;

    // --- cp.async src/dst (2 x 16B per tile per thread) ---
    const int r0 = tid >> 2, ch = tid & 3, r1 = r0 + 64;
    const unsigned d0 = (unsigned)(r0 * 64 + ((ch ^ ((r0 >> 1) & 3)) << 4));
    const unsigned d1 = (unsigned)(r1 * 64 + ((ch ^ ((r1 >> 1) & 3)) << 4));
    const __half* a0p = Ah + (size_t)(m0 + r0) * K + ch * 8;
    const __half* a1p = Ah + (size_t)(m0 + r1) * K + ch * 8;
    const __half* b0p = Bh + (size_t)(n0 + r0) * K + ch * 8;
    const __half* b1p = Bh + (size_t)(n0 + r1) * K + ch * 8;
    const __half* c0p = (NSPLIT == 3) ? Al + (size_t)(m0 + r0) * K + ch * 8 : a0p;
    const __half* c1p = (NSPLIT == 3) ? Al + (size_t)(m0 + r1) * K + ch * 8 : a1p;
    const __half* e0p = (NSPLIT == 3) ? Bl + (size_t)(n0 + r0) * K + ch * 8 : b0p;
    const __half* e1p = (NSPLIT == 3) ? Bl + (size_t)(n0 + r1) * K + ch * 8 : b1p;

    auto issue = [&](int s, int t) {
        if (t < T) {
            unsigned st = sb + (unsigned)s * STB;
            int ko = t * 32;
            cpa16s(st + d0, a0p + ko);
            cpa16s(st + d1, a1p + ko);
            cpa16s(st + TILB + d0, b0p + ko);
            cpa16s(st + TILB + d1, b1p + ko);
            if (NSPLIT == 3) {
                cpa16s(st + 2 * TILB + d0, c0p + ko);
                cpa16s(st + 2 * TILB + d1, c1p + ko);
                cpa16s(st + 3 * TILB + d0, e0p + ko);
                cpa16s(st + 3 * TILB + d1, e1p + ko);
            }
        }
        cpcommit();
    };

    // --- ldmatrix per-lane row bases ---
    const int rr8 = ((lane >> 3) & 1) * 8 + (lane & 7);
    const int qh = lane >> 4;                 // chunk offset within k16
    int aoff[4], asw[4], boff[2], bsw[2];
    #pragma unroll
    for (int mt = 0; mt < 4; mt++) {
        int mr = wm * 64 + mt * 16 + rr8;
        asw[mt] = (mr >> 1) & 3;
        aoff[mt] = mr * 64;                    // bytes
    }
    #pragma unroll
    for (int p = 0; p < 2; p++) {
        int nr = wn * 32 + p * 16 + rr8;
        bsw[p] = (nr >> 1) & 3;
        boff[p] = nr * 64;
    }

    // --- prologue ---
    #pragma unroll
    for (int s = 0; s < STAGES - 1; s++) issue(s, s);

    for (int t = 0; t < T; t++) {
        cpwaitN<STAGES - 2>();
        __syncthreads();
        issue((t + STAGES - 1) % STAGES, t + STAGES - 1);

        unsigned bse = sb + (unsigned)(t % STAGES) * STB;
        unsigned tA  = bse, tB = bse + TILB;
        unsigned tAl = bse + 2 * TILB, tBl = bse + 3 * TILB;

        #pragma unroll
        for (int ks = 0; ks < 2; ks++) {
            int kc = ks * 2 + qh;              // chunk index 0..3
            unsigned ah[4][4], bh[4][2], al[4][4], bl[4][2];
            #pragma unroll
            for (int mt = 0; mt < 4; mt++) {
                unsigned off = (unsigned)(aoff[mt] + ((kc ^ asw[mt]) << 4));
                ldsm4(ah[mt][0], ah[mt][1], ah[mt][2], ah[mt][3], tA + off);
                if (NSPLIT == 3)
                    ldsm4(al[mt][0], al[mt][1], al[mt][2], al[mt][3], tAl + off);
            }
            #pragma unroll
            for (int p = 0; p < 2; p++) {
                unsigned off = (unsigned)(boff[p] + ((kc ^ bsw[p]) << 4));
                unsigned q0, q1, q2, q3;
                ldsm4(q0, q1, q2, q3, tB + off);
                bh[2 * p][0] = q0; bh[2 * p + 1][0] = q1;
                bh[2 * p][1] = q2; bh[2 * p + 1][1] = q3;
                if (NSPLIT == 3) {
                    ldsm4(q0, q1, q2, q3, tBl + off);
                    bl[2 * p][0] = q0; bl[2 * p + 1][0] = q1;
                    bl[2 * p][1] = q2; bl[2 * p + 1][1] = q3;
                }
            }
            #pragma unroll
            for (int mt = 0; mt < 4; mt++)
                #pragma unroll
                for (int nt = 0; nt < 4; nt++) {
                    if (NSPLIT == 3) {
                        mma16(acc[mt][nt], al[mt], bh[nt]);
                        mma16(acc[mt][nt], ah[mt], bl[nt]);
                    }
                    mma16(acc[mt][nt], ah[mt], bh[nt]);
                }
        }
    }
}

// ---------------- K2: projection (M=12544, N=1024, K=2048) --------------------
template<int NSPLIT, int STAGES>
__global__ void __launch_bounds__(256) k_proj_mma(const __half* __restrict__ wh,
                                                  const __half* __restrict__ wl,
                                                  const float* __restrict__ bias,
                                                  float* __restrict__ out) {
    extern __shared__ __align__(16) __half sdyn[];
    unsigned sb = (unsigned)__cvta_generic_to_shared(sdyn);
    int n0 = blockIdx.x * 128, m0 = blockIdx.y * 128;
    float acc[4][4][4] = {};
    gemm_core<NSPLIT, STAGES, CC>(d_xh, d_xl, wh, wl, m0, n0, sb, acc);

    int lane = threadIdx.x & 31, wid = threadIdx.x >> 5;
    int wm = wid & 1, wn = wid >> 1;
    #pragma unroll
    for (int mt = 0; mt < 4; mt++) {
        int r = m0 + wm * 64 + mt * 16 + (lane >> 2);
        #pragma unroll
        for (int nt = 0; nt < 4; nt++) {
            int c = n0 + wn * 32 + nt * 8 + (lane & 3) * 2;
            float b0 = bias[c], b1 = bias[c + 1];
            *(float2*)(out + (size_t)r * II + c) =
                make_float2(acc[mt][nt][0] + b0, acc[mt][nt][1] + b1);
            *(float2*)(out + (size_t)(r + 8) * II + c) =
                make_float2(acc[mt][nt][2] + b0, acc[mt][nt][3] + b1);
        }
    }
}

// ---------------- K6: mask GEMM + epilogue (M=2048, N=B*49, K=1024) -----------
__global__ void __launch_bounds__(256) k_mask_mma(const float* __restrict__ x,
                                                  float* __restrict__ out) {
    extern __shared__ __align__(16) __half sdyn[];
    unsigned sb = (unsigned)__cvta_generic_to_shared(sdyn);
    int n0 = blockIdx.x * 128;   // q blocks (98)
    int m0 = blockIdx.y * 128;   // c blocks (16)
    float acc[4][4][4] = {};
    gemm_core<1, 4, II>(d_mwh, nullptr, d_maph, nullptr, m0, n0, sb, acc);

    int lane = threadIdx.x & 31, wid = threadIdx.x >> 5;
    int wm = wid & 1, wn = wid >> 1;
    #pragma unroll
    for (int mt = 0; mt < 4; mt++) {
        int cbase = m0 + wm * 64 + mt * 16 + (lane >> 2);
        #pragma unroll
        for (int nt = 0; nt < 4; nt++) {
            int qbase = n0 + wn * 32 + nt * 8 + (lane & 3) * 2;
            #pragma unroll
            for (int h = 0; h < 2; h++) {
                int c = cbase + h * 8;
                #pragma unroll
                for (int j = 0; j < 2; j++) {
                    int q = qbase + j;
                    int b = q / 49;
                    int n = q - b * 49;
                    size_t idx = ((size_t)b * CC + c) * NN + n;
                    out[idx] = x[idx] + d_sp[q] * acc[mt][nt][h * 2 + j];
                }
            }
        }
    }
}

// ---------------- K3: attention per batch (fp32), writes map hi ---------------
__global__ void __launch_bounds__(256) k_attn() {
    __shared__ float th_s[4][49][17];
    __shared__ float ph_s[4][49][17];
    __shared__ float sc[49][52];

    const float* gx = d_proj;
    const float* tx = d_proj + (size_t)BN * II;
    const float* px = d_proj + (size_t)2 * BN * II;

    int b = blockIdx.x;
    int tid = threadIdx.x;
    int g = tid >> 6, t = tid & 63;
    int ng = t >> 3, mg = t & 7;
    bool act = (ng < 7) && (mg < 7);

    float acc[7][7] = {};
    for (int kt = 0; kt < 16; kt++) {
        int kb = g * 256 + kt * 16;
        for (int e = t; e < 49 * 16; e += 64) {
            int r = e >> 4, kk = e & 15;
            th_s[g][r][kk] = tx[((size_t)b * NN + r) * II + kb + kk];
            ph_s[g][r][kk] = px[((size_t)b * NN + r) * II + kb + kk];
        }
        __syncthreads();
        if (act) {
            #pragma unroll
            for (int kk = 0; kk < 16; kk++) {
                float av[7], bv[7];
                #pragma unroll
                for (int i = 0; i < 7; i++) av[i] = th_s[g][ng * 7 + i][kk];
                #pragma unroll
                for (int j = 0; j < 7; j++) bv[j] = ph_s[g][mg * 7 + j][kk];
                #pragma unroll
                for (int i = 0; i < 7; i++)
                    #pragma unroll
                    for (int j = 0; j < 7; j++)
                        acc[i][j] += av[i] * bv[j];
            }
        }
        __syncthreads();
    }
    for (int gg = 0; gg < 4; gg++) {
        if (g == gg && act) {
            #pragma unroll
            for (int i = 0; i < 7; i++)
                #pragma unroll
                for (int j = 0; j < 7; j++) {
                    if (gg == 0) sc[ng * 7 + i][mg * 7 + j] = acc[i][j];
                    else         sc[ng * 7 + i][mg * 7 + j] += acc[i][j];
                }
        }
        __syncthreads();
    }
    if (tid < 49) {
        float mx = -1e30f;
        for (int m = 0; m < NN; m++) mx = fmaxf(mx, sc[tid][m]);
        float s = 0.f;
        for (int m = 0; m < NN; m++) {
            float e = expf(sc[tid][m] - mx);
            sc[tid][m] = e; s += e;
        }
        float inv = 1.f / s;
        for (int m = 0; m < NN; m++) sc[tid][m] *= inv;
    }
    __syncthreads();
    for (int op = 0; op < 4; op++) {
        int o = op * 256 + tid;
        float a2[49];
        #pragma unroll
        for (int n = 0; n < NN; n++) a2[n] = 0.f;
        for (int m = 0; m < NN; m++) {
            float gv = gx[((size_t)b * NN + m) * II + o];
            #pragma unroll
            for (int n = 0; n < NN; n++) a2[n] += sc[n][m] * gv;
        }
        for (int n = 0; n < NN; n++)
            d_maph[((size_t)b * NN + n) * II + o] = __float2half_rn(a2[n]);
    }
}

// ---------------- K4: spatial FC partials ------------------------------------
__global__ void __launch_bounds__(256) k_spart(const float* __restrict__ x,
                                               const float* __restrict__ fcw) {
    __shared__ float fc_s[49][65];
    __shared__ float x_s[16][65];
    int b0 = blockIdx.x * 16;
    int ks = blockIdx.y;
    int tid = threadIdx.x;
    int bg = tid >> 5, jg = tid & 31;
    float acc[2][2] = {};
    for (int kc = 0; kc < KPER / 64; kc++) {
        int kb = ks * KPER + kc * 64;
        for (int e = tid; e < 49 * 64; e += 256) {
            int j = e >> 6, kk = e & 63;
            fc_s[j][kk] = fcw[(size_t)j * CN + kb + kk];
        }
        for (int e = tid; e < 16 * 64; e += 256) {
            int bl = e >> 6, kk = e & 63;
            x_s[bl][kk] = x[(size_t)(b0 + bl) * CN + kb + kk];
        }
        __syncthreads();
        #pragma unroll 8
        for (int kk = 0; kk < 64; kk++) {
            float x0 = x_s[bg * 2][kk], x1 = x_s[bg * 2 + 1][kk];
            float f0 = fc_s[jg][kk];
            float f1 = (jg < 17) ? fc_s[jg + 32][kk] : 0.f;
            acc[0][0] += x0 * f0; acc[0][1] += x0 * f1;
            acc[1][0] += x1 * f0; acc[1][1] += x1 * f1;
        }
        __syncthreads();
    }
    #pragma unroll
    for (int i = 0; i < 2; i++) {
        int b = b0 + bg * 2 + i;
        d_spart[((size_t)ks * BB + b) * NN + jg] = acc[i][0];
        if (jg + 32 < NN)
            d_spart[((size_t)ks * BB + b) * NN + jg + 32] = acc[i][1];
    }
}

// ---------------- K5: reduce k-split partials + bias --------------------------
__global__ void k_sred(const float* __restrict__ fcb) {
    int b = blockIdx.x, j = threadIdx.x;
    if (j < NN) {
        float s = fcb[j];
        for (int ks = 0; ks < KSPL; ks++)
            s += d_spart[((size_t)ks * BB + b) * NN + j];
        d_sp[b * NN + j] = s;
    }
}

// ---------------------------------------------------------------------------
extern "C" void kernel_launch(void* const* d_in, const int* in_sizes, int n_in,
                              void* d_out, int out_size) {
    const float* x    = (const float*)d_in[0];
    const float* g_w  = (const float*)d_in[1];
    const float* g_b  = (const float*)d_in[2];
    const float* th_w = (const float*)d_in[3];
    const float* th_b = (const float*)d_in[4];
    const float* ph_w = (const float*)d_in[5];
    const float* ph_b = (const float*)d_in[6];
    const float* W_w  = (const float*)d_in[7];
    const float* fc_w = (const float*)d_in[8];
    const float* fc_b = (const float*)d_in[9];
    float* out = (float*)d_out;
    (void)in_sizes; (void)n_in; (void)out_size;

    __half *p_wh, *p_wl, *p_mwh;
    float* p_proj;
    cudaGetSymbolAddress((void**)&p_wh,  d_wh);
    cudaGetSymbolAddress((void**)&p_wl,  d_wl);
    cudaGetSymbolAddress((void**)&p_mwh, d_mwh);
    cudaGetSymbolAddress((void**)&p_proj, d_proj);

    // dynamic smem: NSPLIT3 = 3 stages * 4 tiles * 8KB = 96KB
    //               NSPLIT1 = 4 stages * 2 tiles * 8KB = 64KB
    const int SM3 = 3 * 4 * 8192;
    const int SM1 = 4 * 2 * 8192;
    cudaFuncSetAttribute(k_proj_mma<3, 3>, cudaFuncAttributeMaxDynamicSharedMemorySize, SM3);
    cudaFuncSetAttribute(k_proj_mma<1, 4>, cudaFuncAttributeMaxDynamicSharedMemorySize, SM1);
    cudaFuncSetAttribute(k_mask_mma,       cudaFuncAttributeMaxDynamicSharedMemorySize, SM1);

    const int WSZ = II * CC;  // 2M
    k_split1<<<(WSZ + 255) / 256, 256>>>(g_w,  p_wh, WSZ);
    k_split <<<(WSZ + 255) / 256, 256>>>(th_w, p_wh + WSZ,     p_wl + WSZ,     WSZ);
    k_split <<<(WSZ + 255) / 256, 256>>>(ph_w, p_wh + 2 * WSZ, p_wl + 2 * WSZ, WSZ);
    k_split1<<<(WSZ + 255) / 256, 256>>>(W_w,  p_mwh, WSZ);

    k_transpose_split<<<dim3(CC / 64, BB), 256>>>(x);

    dim3 pg(II / 128, BN / 128);   // (8, 98)
    k_proj_mma<1, 4><<<pg, 256, SM1>>>(p_wh,           nullptr,        g_b,  p_proj);
    k_proj_mma<3, 3><<<pg, 256, SM3>>>(p_wh + WSZ,     p_wl + WSZ,     th_b, p_proj + (size_t)BN * II);
    k_proj_mma<3, 3><<<pg, 256, SM3>>>(p_wh + 2 * WSZ, p_wl + 2 * WSZ, ph_b, p_proj + (size_t)2 * BN * II);

    k_attn<<<BB, 256>>>();

    k_spart<<<dim3(BB / 16, KSPL), 256>>>(x, fc_w);
    k_sred<<<BB, 64>>>(fc_b);

    k_mask_mma<<<dim3(BN / 128, CC / 128), 256, SM1>>>(x, out);
}

// round 7
// speedup vs baseline: 3.1832x; 1.0426x over previous
#include <cuda_runtime.h>
#include <cuda_fp16.h>

// ---------------------------------------------------------------------------
// ModulatedAttLayer  B=256, C=2048, H=W=7 (N=49), INTER=1024
//
// R7: mma.sync fp16 GEMMs (tcgen05 unavailable: harness PTX targets sm_103),
//     ldmatrix + swizzled smem + cp.async pipeline; register-lean inner loop
//     + __launch_bounds__(256,2) for 2 CTAs/SM (latency hiding).
//   theta/phi projections : fp16x3 split; g/mask : single fp16.
// ---------------------------------------------------------------------------

#define BB   256
#define CC   2048
#define NN   49
#define II   1024
#define BN   (BB*NN)      // 12544
#define CN   (CC*NN)      // 100352
#define KSPL 16
#define KPER (CN/KSPL)    // 6272

__device__ __align__(16) __half d_xh[(size_t)BN*CC];   // xT hi
__device__ __align__(16) __half d_xl[(size_t)BN*CC];   // xT lo
__device__ __align__(16) __half d_wh[(size_t)3*II*CC]; // g/theta/phi weights hi
__device__ __align__(16) __half d_wl[(size_t)3*II*CC]; // lo (theta/phi used)
__device__ __align__(16) __half d_mwh[(size_t)CC*II];  // W_w hi
__device__ __align__(16) __half d_maph[(size_t)BN*II]; // map hi
__device__ float d_proj[(size_t)3*BN*II];              // gx/tx/px fp32
__device__ float d_spart[(size_t)KSPL*BB*NN];
__device__ float d_sp[(size_t)BB*NN];

// ---------------- helpers ----------------------------------------------------
__device__ __forceinline__ void splith(float v, __half& h, __half& l) {
    h = __float2half_rn(v);
    l = __float2half_rn(v - __half2float(h));
}

__device__ __forceinline__ void mma16(float* d, const unsigned* a, const unsigned* b) {
    asm volatile(
        "mma.sync.aligned.m16n8k16.row.col.f32.f16.f16.f32 "
        "{%0,%1,%2,%3}, {%4,%5,%6,%7}, {%8,%9}, {%0,%1,%2,%3};\n"
        : "+f"(d[0]), "+f"(d[1]), "+f"(d[2]), "+f"(d[3])
        : "r"(a[0]), "r"(a[1]), "r"(a[2]), "r"(a[3]), "r"(b[0]), "r"(b[1]));
}

__device__ __forceinline__ void cpa16s(unsigned s, const __half* g) {
    asm volatile("cp.async.cg.shared.global [%0], [%1], 16;\n" :: "r"(s), "l"(g));
}
__device__ __forceinline__ void cpcommit() { asm volatile("cp.async.commit_group;\n"); }
template<int N>
__device__ __forceinline__ void cpwaitN() {
    asm volatile("cp.async.wait_group %0;\n" :: "n"(N) : "memory");
}
__device__ __forceinline__ void ldsm4(unsigned& r0, unsigned& r1, unsigned& r2,
                                      unsigned& r3, unsigned addr) {
    asm volatile("ldmatrix.sync.aligned.m8n8.x4.shared.b16 {%0,%1,%2,%3}, [%4];"
                 : "=r"(r0), "=r"(r1), "=r"(r2), "=r"(r3) : "r"(addr));
}

// ---------------- K0: split fp32 -> fp16 hi/lo --------------------------------
__global__ void k_split(const float* __restrict__ src, __half* __restrict__ hi,
                        __half* __restrict__ lo, int n) {
    int i = blockIdx.x * 256 + threadIdx.x;
    if (i < n) splith(src[i], hi[i], lo[i]);
}
__global__ void k_split1(const float* __restrict__ src, __half* __restrict__ hi, int n) {
    int i = blockIdx.x * 256 + threadIdx.x;
    if (i < n) hi[i] = __float2half_rn(src[i]);
}

// ---------------- K1: transpose + split x[b,c,n] -> xT hi/lo [b*49+n, c] ------
__global__ void k_transpose_split(const float* __restrict__ x) {
    __shared__ float s[64][50];
    int b = blockIdx.y, c0 = blockIdx.x * 64;
    const float* xb = x + (size_t)b * CN;
    for (int e = threadIdx.x; e < 64 * NN; e += 256) {
        int cl = e / NN, n = e - cl * NN;
        s[cl][n] = xb[(c0 + cl) * NN + n];
    }
    __syncthreads();
    for (int e = threadIdx.x; e < 64 * NN; e += 256) {
        int n = e >> 6, cl = e & 63;
        size_t o = ((size_t)b * NN + n) * CC + c0 + cl;
        splith(s[cl][n], d_xh[o], d_xl[o]);
    }
}

// ---------------- GEMM core: acc[m,n] += A[m,k]*B[n,k] ------------------------
// CTA 128x128, k-step 32, 8 warps (2m x 4n), warp tile 64x32.
// smem tile: 128 rows x 32 halves (64B rows), 16B chunks XOR-swizzled by
// chunk' = chunk ^ ((row>>1)&3)  -> LDSM phases conflict-free.
// Register-lean: B frags resident, A frags streamed per-mt.
template<int NSPLIT, int STAGES, int K>
__device__ __forceinline__ void gemm_core(
    const __half* __restrict__ Ah, const __half* __restrict__ Al,
    const __half* __restrict__ Bh, const __half* __restrict__ Bl,
    int m0, int n0, unsigned sb, float acc[4][4][4])
{
    constexpr int NT   = (NSPLIT == 3) ? 4 : 2;
    constexpr int TILB = 128 * 32 * 2;   // tile bytes (8KB)
    constexpr int STB  = NT * TILB;      // stage bytes
    constexpr int T    = K / 32;
    const int tid = threadIdx.x, lane = tid & 31, wid = tid >> 5;
    const int wm = wid & 1, wn = wid >> 1;

    // --- cp.async src/dst (2 x 16B per tile per thread) ---
    const int r0 = tid >> 2, ch = tid & 3, r1 = r0 + 64;
    const unsigned d0 = (unsigned)(r0 * 64 + ((ch ^ ((r0 >> 1) & 3)) << 4));
    const unsigned d1 = (unsigned)(r1 * 64 + ((ch ^ ((r1 >> 1) & 3)) << 4));
    const __half* a0p = Ah + (size_t)(m0 + r0) * K + ch * 8;
    const __half* a1p = Ah + (size_t)(m0 + r1) * K + ch * 8;
    const __half* b0p = Bh + (size_t)(n0 + r0) * K + ch * 8;
    const __half* b1p = Bh + (size_t)(n0 + r1) * K + ch * 8;
    const __half* c0p = (NSPLIT == 3) ? Al + (size_t)(m0 + r0) * K + ch * 8 : a0p;
    const __half* c1p = (NSPLIT == 3) ? Al + (size_t)(m0 + r1) * K + ch * 8 : a1p;
    const __half* e0p = (NSPLIT == 3) ? Bl + (size_t)(n0 + r0) * K + ch * 8 : b0p;
    const __half* e1p = (NSPLIT == 3) ? Bl + (size_t)(n0 + r1) * K + ch * 8 : b1p;

    auto issue = [&](int s, int t) {
        if (t < T) {
            unsigned st = sb + (unsigned)s * STB;
            int ko = t * 32;
            cpa16s(st + d0, a0p + ko);
            cpa16s(st + d1, a1p + ko);
            cpa16s(st + TILB + d0, b0p + ko);
            cpa16s(st + TILB + d1, b1p + ko);
            if (NSPLIT == 3) {
                cpa16s(st + 2 * TILB + d0, c0p + ko);
                cpa16s(st + 2 * TILB + d1, c1p + ko);
                cpa16s(st + 3 * TILB + d0, e0p + ko);
                cpa16s(st + 3 * TILB + d1, e1p + ko);
            }
        }
        cpcommit();
    };

    // --- ldmatrix per-lane row bases ---
    const int rr8 = ((lane >> 3) & 1) * 8 + (lane & 7);
    const int qh = lane >> 4;                 // chunk offset within k16
    int aoff[4], asw[4], boff[2], bsw[2];
    #pragma unroll
    for (int mt = 0; mt < 4; mt++) {
        int mr = wm * 64 + mt * 16 + rr8;
        asw[mt] = (mr >> 1) & 3;
        aoff[mt] = mr * 64;                    // bytes
    }
    #pragma unroll
    for (int p = 0; p < 2; p++) {
        int nr = wn * 32 + p * 16 + rr8;
        bsw[p] = (nr >> 1) & 3;
        boff[p] = nr * 64;
    }

    // --- prologue ---
    #pragma unroll
    for (int s = 0; s < STAGES - 1; s++) issue(s, s);

    for (int t = 0; t < T; t++) {
        cpwaitN<STAGES - 2>();
        __syncthreads();
        issue((t + STAGES - 1) % STAGES, t + STAGES - 1);

        unsigned bse = sb + (unsigned)(t % STAGES) * STB;
        unsigned tA  = bse, tB = bse + TILB;
        unsigned tAl = bse + 2 * TILB, tBl = bse + 3 * TILB;

        #pragma unroll
        for (int ks = 0; ks < 2; ks++) {
            int kc = ks * 2 + qh;              // chunk index 0..3
            // B fragments resident for this k16
            unsigned bh[4][2], bl[4][2];
            #pragma unroll
            for (int p = 0; p < 2; p++) {
                unsigned off = (unsigned)(boff[p] + ((kc ^ bsw[p]) << 4));
                unsigned q0, q1, q2, q3;
                ldsm4(q0, q1, q2, q3, tB + off);
                bh[2 * p][0] = q0; bh[2 * p + 1][0] = q1;
                bh[2 * p][1] = q2; bh[2 * p + 1][1] = q3;
                if (NSPLIT == 3) {
                    ldsm4(q0, q1, q2, q3, tBl + off);
                    bl[2 * p][0] = q0; bl[2 * p + 1][0] = q1;
                    bl[2 * p][1] = q2; bl[2 * p + 1][1] = q3;
                }
            }
            // A fragments streamed per-mt (keeps live regs low)
            #pragma unroll
            for (int mt = 0; mt < 4; mt++) {
                unsigned off = (unsigned)(aoff[mt] + ((kc ^ asw[mt]) << 4));
                unsigned ah[4], al[4];
                ldsm4(ah[0], ah[1], ah[2], ah[3], tA + off);
                if (NSPLIT == 3)
                    ldsm4(al[0], al[1], al[2], al[3], tAl + off);
                #pragma unroll
                for (int nt = 0; nt < 4; nt++) {
                    if (NSPLIT == 3) {
                        mma16(acc[mt][nt], al, bh[nt]);
                        mma16(acc[mt][nt], ah, bl[nt]);
                    }
                    mma16(acc[mt][nt], ah, bh[nt]);
                }
            }
        }
    }
}

// ---------------- K2: projection (M=12544, N=1024, K=2048) --------------------
template<int NSPLIT, int STAGES>
__global__ void __launch_bounds__(256, 2) k_proj_mma(const __half* __restrict__ wh,
                                                     const __half* __restrict__ wl,
                                                     const float* __restrict__ bias,
                                                     float* __restrict__ out) {
    extern __shared__ __align__(16) __half sdyn[];
    unsigned sb = (unsigned)__cvta_generic_to_shared(sdyn);
    int n0 = blockIdx.x * 128, m0 = blockIdx.y * 128;
    float acc[4][4][4] = {};
    gemm_core<NSPLIT, STAGES, CC>(d_xh, d_xl, wh, wl, m0, n0, sb, acc);

    int lane = threadIdx.x & 31, wid = threadIdx.x >> 5;
    int wm = wid & 1, wn = wid >> 1;
    #pragma unroll
    for (int mt = 0; mt < 4; mt++) {
        int r = m0 + wm * 64 + mt * 16 + (lane >> 2);
        #pragma unroll
        for (int nt = 0; nt < 4; nt++) {
            int c = n0 + wn * 32 + nt * 8 + (lane & 3) * 2;
            float b0 = bias[c], b1 = bias[c + 1];
            *(float2*)(out + (size_t)r * II + c) =
                make_float2(acc[mt][nt][0] + b0, acc[mt][nt][1] + b1);
            *(float2*)(out + (size_t)(r + 8) * II + c) =
                make_float2(acc[mt][nt][2] + b0, acc[mt][nt][3] + b1);
        }
    }
}

// ---------------- K6: mask GEMM + epilogue (M=2048, N=B*49, K=1024) -----------
__global__ void __launch_bounds__(256, 2) k_mask_mma(const float* __restrict__ x,
                                                     float* __restrict__ out) {
    extern __shared__ __align__(16) __half sdyn[];
    unsigned sb = (unsigned)__cvta_generic_to_shared(sdyn);
    int n0 = blockIdx.x * 128;   // q blocks (98)
    int m0 = blockIdx.y * 128;   // c blocks (16)
    float acc[4][4][4] = {};
    gemm_core<1, 4, II>(d_mwh, nullptr, d_maph, nullptr, m0, n0, sb, acc);

    int lane = threadIdx.x & 31, wid = threadIdx.x >> 5;
    int wm = wid & 1, wn = wid >> 1;
    #pragma unroll
    for (int mt = 0; mt < 4; mt++) {
        int cbase = m0 + wm * 64 + mt * 16 + (lane >> 2);
        #pragma unroll
        for (int nt = 0; nt < 4; nt++) {
            int qbase = n0 + wn * 32 + nt * 8 + (lane & 3) * 2;
            #pragma unroll
            for (int h = 0; h < 2; h++) {
                int c = cbase + h * 8;
                #pragma unroll
                for (int j = 0; j < 2; j++) {
                    int q = qbase + j;
                    int b = q / 49;
                    int n = q - b * 49;
                    size_t idx = ((size_t)b * CC + c) * NN + n;
                    out[idx] = x[idx] + d_sp[q] * acc[mt][nt][h * 2 + j];
                }
            }
        }
    }
}

// ---------------- K3: attention per batch (fp32), writes map hi ---------------
__global__ void __launch_bounds__(256) k_attn() {
    __shared__ float th_s[4][49][17];
    __shared__ float ph_s[4][49][17];
    __shared__ float sc[49][52];

    const float* gx = d_proj;
    const float* tx = d_proj + (size_t)BN * II;
    const float* px = d_proj + (size_t)2 * BN * II;

    int b = blockIdx.x;
    int tid = threadIdx.x;
    int g = tid >> 6, t = tid & 63;
    int ng = t >> 3, mg = t & 7;
    bool act = (ng < 7) && (mg < 7);

    float acc[7][7] = {};
    for (int kt = 0; kt < 16; kt++) {
        int kb = g * 256 + kt * 16;
        for (int e = t; e < 49 * 16; e += 64) {
            int r = e >> 4, kk = e & 15;
            th_s[g][r][kk] = tx[((size_t)b * NN + r) * II + kb + kk];
            ph_s[g][r][kk] = px[((size_t)b * NN + r) * II + kb + kk];
        }
        __syncthreads();
        if (act) {
            #pragma unroll
            for (int kk = 0; kk < 16; kk++) {
                float av[7], bv[7];
                #pragma unroll
                for (int i = 0; i < 7; i++) av[i] = th_s[g][ng * 7 + i][kk];
                #pragma unroll
                for (int j = 0; j < 7; j++) bv[j] = ph_s[g][mg * 7 + j][kk];
                #pragma unroll
                for (int i = 0; i < 7; i++)
                    #pragma unroll
                    for (int j = 0; j < 7; j++)
                        acc[i][j] += av[i] * bv[j];
            }
        }
        __syncthreads();
    }
    for (int gg = 0; gg < 4; gg++) {
        if (g == gg && act) {
            #pragma unroll
            for (int i = 0; i < 7; i++)
                #pragma unroll
                for (int j = 0; j < 7; j++) {
                    if (gg == 0) sc[ng * 7 + i][mg * 7 + j] = acc[i][j];
                    else         sc[ng * 7 + i][mg * 7 + j] += acc[i][j];
                }
        }
        __syncthreads();
    }
    if (tid < 49) {
        float mx = -1e30f;
        for (int m = 0; m < NN; m++) mx = fmaxf(mx, sc[tid][m]);
        float s = 0.f;
        for (int m = 0; m < NN; m++) {
            float e = expf(sc[tid][m] - mx);
            sc[tid][m] = e; s += e;
        }
        float inv = 1.f / s;
        for (int m = 0; m < NN; m++) sc[tid][m] *= inv;
    }
    __syncthreads();
    for (int op = 0; op < 4; op++) {
        int o = op * 256 + tid;
        float a2[49];
        #pragma unroll
        for (int n = 0; n < NN; n++) a2[n] = 0.f;
        for (int m = 0; m < NN; m++) {
            float gv = gx[((size_t)b * NN + m) * II + o];
            #pragma unroll
            for (int n = 0; n < NN; n++) a2[n] += sc[n][m] * gv;
        }
        for (int n = 0; n < NN; n++)
            d_maph[((size_t)b * NN + n) * II + o] = __float2half_rn(a2[n]);
    }
}

// ---------------- K4: spatial FC partials ------------------------------------
__global__ void __launch_bounds__(256) k_spart(const float* __restrict__ x,
                                               const float* __restrict__ fcw) {
    __shared__ float fc_s[49][65];
    __shared__ float x_s[16][65];
    int b0 = blockIdx.x * 16;
    int ks = blockIdx.y;
    int tid = threadIdx.x;
    int bg = tid >> 5, jg = tid & 31;
    float acc[2][2] = {};
    for (int kc = 0; kc < KPER / 64; kc++) {
        int kb = ks * KPER + kc * 64;
        for (int e = tid; e < 49 * 64; e += 256) {
            int j = e >> 6, kk = e & 63;
            fc_s[j][kk] = fcw[(size_t)j * CN + kb + kk];
        }
        for (int e = tid; e < 16 * 64; e += 256) {
            int bl = e >> 6, kk = e & 63;
            x_s[bl][kk] = x[(size_t)(b0 + bl) * CN + kb + kk];
        }
        __syncthreads();
        #pragma unroll 8
        for (int kk = 0; kk < 64; kk++) {
            float x0 = x_s[bg * 2][kk], x1 = x_s[bg * 2 + 1][kk];
            float f0 = fc_s[jg][kk];
            float f1 = (jg < 17) ? fc_s[jg + 32][kk] : 0.f;
            acc[0][0] += x0 * f0; acc[0][1] += x0 * f1;
            acc[1][0] += x1 * f0; acc[1][1] += x1 * f1;
        }
        __syncthreads();
    }
    #pragma unroll
    for (int i = 0; i < 2; i++) {
        int b = b0 + bg * 2 + i;
        d_spart[((size_t)ks * BB + b) * NN + jg] = acc[i][0];
        if (jg + 32 < NN)
            d_spart[((size_t)ks * BB + b) * NN + jg + 32] = acc[i][1];
    }
}

// ---------------- K5: reduce k-split partials + bias --------------------------
__global__ void k_sred(const float* __restrict__ fcb) {
    int b = blockIdx.x, j = threadIdx.x;
    if (j < NN) {
        float s = fcb[j];
        for (int ks = 0; ks < KSPL; ks++)
            s += d_spart[((size_t)ks * BB + b) * NN + j];
        d_sp[b * NN + j] = s;
    }
}

// ---------------------------------------------------------------------------
extern "C" void kernel_launch(void* const* d_in, const int* in_sizes, int n_in,
                              void* d_out, int out_size) {
    const float* x    = (const float*)d_in[0];
    const float* g_w  = (const float*)d_in[1];
    const float* g_b  = (const float*)d_in[2];
    const float* th_w = (const float*)d_in[3];
    const float* th_b = (const float*)d_in[4];
    const float* ph_w = (const float*)d_in[5];
    const float* ph_b = (const float*)d_in[6];
    const float* W_w  = (const float*)d_in[7];
    const float* fc_w = (const float*)d_in[8];
    const float* fc_b = (const float*)d_in[9];
    float* out = (float*)d_out;
    (void)in_sizes; (void)n_in; (void)out_size;

    __half *p_wh, *p_wl, *p_mwh;
    float* p_proj;
    cudaGetSymbolAddress((void**)&p_wh,  d_wh);
    cudaGetSymbolAddress((void**)&p_wl,  d_wl);
    cudaGetSymbolAddress((void**)&p_mwh, d_mwh);
    cudaGetSymbolAddress((void**)&p_proj, d_proj);

    // dynamic smem: NSPLIT3 = 3 stages * 4 tiles * 8KB = 96KB (2 CTAs -> 192KB/SM)
    //               NSPLIT1 = 4 stages * 2 tiles * 8KB = 64KB (2 CTAs -> 128KB/SM)
    const int SM3 = 3 * 4 * 8192;
    const int SM1 = 4 * 2 * 8192;
    cudaFuncSetAttribute(k_proj_mma<3, 3>, cudaFuncAttributeMaxDynamicSharedMemorySize, SM3);
    cudaFuncSetAttribute(k_proj_mma<1, 4>, cudaFuncAttributeMaxDynamicSharedMemorySize, SM1);
    cudaFuncSetAttribute(k_mask_mma,       cudaFuncAttributeMaxDynamicSharedMemorySize, SM1);

    const int WSZ = II * CC;  // 2M
    k_split1<<<(WSZ + 255) / 256, 256>>>(g_w,  p_wh, WSZ);
    k_split <<<(WSZ + 255) / 256, 256>>>(th_w, p_wh + WSZ,     p_wl + WSZ,     WSZ);
    k_split <<<(WSZ + 255) / 256, 256>>>(ph_w, p_wh + 2 * WSZ, p_wl + 2 * WSZ, WSZ);
    k_split1<<<(WSZ + 255) / 256, 256>>>(W_w,  p_mwh, WSZ);

    k_transpose_split<<<dim3(CC / 64, BB), 256>>>(x);

    dim3 pg(II / 128, BN / 128);   // (8, 98)
    k_proj_mma<1, 4><<<pg, 256, SM1>>>(p_wh,           nullptr,        g_b,  p_proj);
    k_proj_mma<3, 3><<<pg, 256, SM3>>>(p_wh + WSZ,     p_wl + WSZ,     th_b, p_proj + (size_t)BN * II);
    k_proj_mma<3, 3><<<pg, 256, SM3>>>(p_wh + 2 * WSZ, p_wl + 2 * WSZ, ph_b, p_proj + (size_t)2 * BN * II);

    k_attn<<<BB, 256>>>();

    k_spart<<<dim3(BB / 16, KSPL), 256>>>(x, fc_w);
    k_sred<<<BB, 64>>>(fc_b);

    k_mask_mma<<<dim3(BN / 128, CC / 128), 256, SM1>>>(x, out);
}

// round 8
// speedup vs baseline: 3.4197x; 1.0743x over previous
#include <cuda_runtime.h>
#include <cuda_fp16.h>

// ---------------------------------------------------------------------------
// ModulatedAttLayer  B=256, C=2048, H=W=7 (N=49), INTER=1024
//
// R8: mma.sync fp16 GEMMs; register-dieted core (pointer deltas) so
//     __launch_bounds__(256,2) runs spill-free at 2 CTAs/SM.
//     Launches reordered so ncu -s 5 captures proj3.
//   theta/phi projections : fp16x3 split; g/mask : single fp16.
// ---------------------------------------------------------------------------

#define BB   256
#define CC   2048
#define NN   49
#define II   1024
#define BN   (BB*NN)      // 12544
#define CN   (CC*NN)      // 100352
#define KSPL 32
#define KPER (CN/KSPL)    // 3136

__device__ __align__(16) __half d_xh[(size_t)BN*CC];   // xT hi
__device__ __align__(16) __half d_xl[(size_t)BN*CC];   // xT lo
__device__ __align__(16) __half d_wh[(size_t)3*II*CC]; // g/theta/phi weights hi
__device__ __align__(16) __half d_wl[(size_t)3*II*CC]; // lo (theta/phi used)
__device__ __align__(16) __half d_mwh[(size_t)CC*II];  // W_w hi
__device__ __align__(16) __half d_maph[(size_t)BN*II]; // map hi
__device__ float d_proj[(size_t)3*BN*II];              // gx/tx/px fp32
__device__ float d_spart[(size_t)KSPL*BB*NN];
__device__ float d_sp[(size_t)BB*NN];

// ---------------- helpers ----------------------------------------------------
__device__ __forceinline__ void splith(float v, __half& h, __half& l) {
    h = __float2half_rn(v);
    l = __float2half_rn(v - __half2float(h));
}

__device__ __forceinline__ void mma16(float* d, const unsigned* a, const unsigned* b) {
    asm volatile(
        "mma.sync.aligned.m16n8k16.row.col.f32.f16.f16.f32 "
        "{%0,%1,%2,%3}, {%4,%5,%6,%7}, {%8,%9}, {%0,%1,%2,%3};\n"
        : "+f"(d[0]), "+f"(d[1]), "+f"(d[2]), "+f"(d[3])
        : "r"(a[0]), "r"(a[1]), "r"(a[2]), "r"(a[3]), "r"(b[0]), "r"(b[1]));
}

__device__ __forceinline__ void cpa16s(unsigned s, const __half* g) {
    asm volatile("cp.async.cg.shared.global [%0], [%1], 16;\n" :: "r"(s), "l"(g));
}
__device__ __forceinline__ void cpcommit() { asm volatile("cp.async.commit_group;\n"); }
template<int N>
__device__ __forceinline__ void cpwaitN() {
    asm volatile("cp.async.wait_group %0;\n" :: "n"(N) : "memory");
}
__device__ __forceinline__ void ldsm4(unsigned& r0, unsigned& r1, unsigned& r2,
                                      unsigned& r3, unsigned addr) {
    asm volatile("ldmatrix.sync.aligned.m8n8.x4.shared.b16 {%0,%1,%2,%3}, [%4];"
                 : "=r"(r0), "=r"(r1), "=r"(r2), "=r"(r3) : "r"(addr));
}

// ---------------- K0: split fp32 -> fp16 hi/lo --------------------------------
__global__ void k_split(const float* __restrict__ src, __half* __restrict__ hi,
                        __half* __restrict__ lo, int n) {
    int i = blockIdx.x * 256 + threadIdx.x;
    if (i < n) splith(src[i], hi[i], lo[i]);
}
__global__ void k_split1(const float* __restrict__ src, __half* __restrict__ hi, int n) {
    int i = blockIdx.x * 256 + threadIdx.x;
    if (i < n) hi[i] = __float2half_rn(src[i]);
}

// ---------------- K1: transpose + split x[b,c,n] -> xT hi/lo [b*49+n, c] ------
__global__ void k_transpose_split(const float* __restrict__ x) {
    __shared__ float s[64][50];
    int b = blockIdx.y, c0 = blockIdx.x * 64;
    const float* xb = x + (size_t)b * CN;
    for (int e = threadIdx.x; e < 64 * NN; e += 256) {
        int cl = e / NN, n = e - cl * NN;
        s[cl][n] = xb[(c0 + cl) * NN + n];
    }
    __syncthreads();
    for (int e = threadIdx.x; e < 64 * NN; e += 256) {
        int n = e >> 6, cl = e & 63;
        size_t o = ((size_t)b * NN + n) * CC + c0 + cl;
        splith(s[cl][n], d_xh[o], d_xl[o]);
    }
}

// ---------------- GEMM core: acc[m,n] += A[m,k]*B[n,k] ------------------------
// CTA 128x128, k-step 32, 8 warps (2m x 4n), warp tile 64x32.
// Register-lean: 4 global pointers + 2 lo-deltas; B frags resident, A streamed.
// smem: 128x32-half tiles (64B rows), chunk XOR swizzle; one barrier/k-step.
template<int NSPLIT, int STAGES, int K>
__device__ __forceinline__ void gemm_core(
    const __half* __restrict__ A,    // = Ah + m0*K
    ptrdiff_t dAl,                   // Al - Ah  (elements)
    const __half* __restrict__ B,    // = Bh + n0*K
    ptrdiff_t dBl,                   // Bl - Bh
    unsigned sb, float acc[4][4][4])
{
    constexpr int NT   = (NSPLIT == 3) ? 4 : 2;
    constexpr int TILB = 128 * 32 * 2;   // tile bytes (8KB)
    constexpr int STB  = NT * TILB;      // stage bytes
    constexpr int T    = K / 32;
    const int tid = threadIdx.x, lane = tid & 31, wid = tid >> 5;
    const int wm = wid & 1, wn = wid >> 1;

    // --- cp.async src/dst (2 x 16B per tile per thread) ---
    const int r0 = tid >> 2, ch = tid & 3, r1 = r0 + 64;
    const unsigned d0 = (unsigned)(r0 * 64 + ((ch ^ ((r0 >> 1) & 3)) << 4));
    const unsigned d1 = (unsigned)(r1 * 64 + ((ch ^ ((r1 >> 1) & 3)) << 4));
    const __half* a0p = A + (size_t)r0 * K + ch * 8;
    const __half* a1p = A + (size_t)r1 * K + ch * 8;
    const __half* b0p = B + (size_t)r0 * K + ch * 8;
    const __half* b1p = B + (size_t)r1 * K + ch * 8;

    auto issue = [&](int s, int t) {
        if (t < T) {
            unsigned st = sb + (unsigned)s * STB;
            int ko = t * 32;
            cpa16s(st + d0, a0p + ko);
            cpa16s(st + d1, a1p + ko);
            cpa16s(st + TILB + d0, b0p + ko);
            cpa16s(st + TILB + d1, b1p + ko);
            if (NSPLIT == 3) {
                cpa16s(st + 2 * TILB + d0, a0p + dAl + ko);
                cpa16s(st + 2 * TILB + d1, a1p + dAl + ko);
                cpa16s(st + 3 * TILB + d0, b0p + dBl + ko);
                cpa16s(st + 3 * TILB + d1, b1p + dBl + ko);
            }
        }
        cpcommit();
    };

    // --- ldmatrix per-lane row bases ---
    const int rr8 = ((lane >> 3) & 1) * 8 + (lane & 7);
    const int qh = lane >> 4;                 // chunk offset within k16
    int aoff[4], asw[4], boff[2], bsw[2];
    #pragma unroll
    for (int mt = 0; mt < 4; mt++) {
        int mr = wm * 64 + mt * 16 + rr8;
        asw[mt] = (mr >> 1) & 3;
        aoff[mt] = mr * 64;                    // bytes
    }
    #pragma unroll
    for (int p = 0; p < 2; p++) {
        int nr = wn * 32 + p * 16 + rr8;
        bsw[p] = (nr >> 1) & 3;
        boff[p] = nr * 64;
    }

    // --- prologue ---
    #pragma unroll
    for (int s = 0; s < STAGES - 1; s++) issue(s, s);

    for (int t = 0; t < T; t++) {
        cpwaitN<STAGES - 2>();
        __syncthreads();
        issue((t + STAGES - 1) % STAGES, t + STAGES - 1);

        unsigned bse = sb + (unsigned)(t % STAGES) * STB;
        unsigned tA  = bse, tB = bse + TILB;
        unsigned tAl = bse + 2 * TILB, tBl = bse + 3 * TILB;

        #pragma unroll
        for (int ks = 0; ks < 2; ks++) {
            int kc = ks * 2 + qh;              // chunk index 0..3
            // B fragments resident for this k16
            unsigned bh[4][2], bl[4][2];
            #pragma unroll
            for (int p = 0; p < 2; p++) {
                unsigned off = (unsigned)(boff[p] + ((kc ^ bsw[p]) << 4));
                unsigned q0, q1, q2, q3;
                ldsm4(q0, q1, q2, q3, tB + off);
                bh[2 * p][0] = q0; bh[2 * p + 1][0] = q1;
                bh[2 * p][1] = q2; bh[2 * p + 1][1] = q3;
                if (NSPLIT == 3) {
                    ldsm4(q0, q1, q2, q3, tBl + off);
                    bl[2 * p][0] = q0; bl[2 * p + 1][0] = q1;
                    bl[2 * p][1] = q2; bl[2 * p + 1][1] = q3;
                }
            }
            // A fragments streamed per-mt (keeps live regs low)
            #pragma unroll
            for (int mt = 0; mt < 4; mt++) {
                unsigned off = (unsigned)(aoff[mt] + ((kc ^ asw[mt]) << 4));
                unsigned ah[4], al[4];
                ldsm4(ah[0], ah[1], ah[2], ah[3], tA + off);
                if (NSPLIT == 3)
                    ldsm4(al[0], al[1], al[2], al[3], tAl + off);
                #pragma unroll
                for (int nt = 0; nt < 4; nt++) {
                    if (NSPLIT == 3) {
                        mma16(acc[mt][nt], al, bh[nt]);
                        mma16(acc[mt][nt], ah, bl[nt]);
                    }
                    mma16(acc[mt][nt], ah, bh[nt]);
                }
            }
        }
    }
}

// ---------------- K2: projection (M=12544, N=1024, K=2048) --------------------
template<int NSPLIT, int STAGES>
__global__ void __launch_bounds__(256, 2) k_proj_mma(const __half* __restrict__ wh,
                                                     ptrdiff_t dwl,
                                                     const float* __restrict__ bias,
                                                     float* __restrict__ out) {
    extern __shared__ __align__(16) __half sdyn[];
    unsigned sb = (unsigned)__cvta_generic_to_shared(sdyn);
    int n0 = blockIdx.x * 128, m0 = blockIdx.y * 128;
    float acc[4][4][4] = {};
    gemm_core<NSPLIT, STAGES, CC>(d_xh + (size_t)m0 * CC, d_xl - d_xh,
                                  wh + (size_t)n0 * CC, dwl, sb, acc);

    int lane = threadIdx.x & 31, wid = threadIdx.x >> 5;
    int wm = wid & 1, wn = wid >> 1;
    #pragma unroll
    for (int mt = 0; mt < 4; mt++) {
        int r = m0 + wm * 64 + mt * 16 + (lane >> 2);
        #pragma unroll
        for (int nt = 0; nt < 4; nt++) {
            int c = n0 + wn * 32 + nt * 8 + (lane & 3) * 2;
            float b0 = bias[c], b1 = bias[c + 1];
            *(float2*)(out + (size_t)r * II + c) =
                make_float2(acc[mt][nt][0] + b0, acc[mt][nt][1] + b1);
            *(float2*)(out + (size_t)(r + 8) * II + c) =
                make_float2(acc[mt][nt][2] + b0, acc[mt][nt][3] + b1);
        }
    }
}

// ---------------- K6: mask GEMM + epilogue (M=2048, N=B*49, K=1024) -----------
__global__ void __launch_bounds__(256, 2) k_mask_mma(const float* __restrict__ x,
                                                     float* __restrict__ out) {
    extern __shared__ __align__(16) __half sdyn[];
    unsigned sb = (unsigned)__cvta_generic_to_shared(sdyn);
    int n0 = blockIdx.x * 128;   // q blocks (98)
    int m0 = blockIdx.y * 128;   // c blocks (16)
    float acc[4][4][4] = {};
    gemm_core<1, 4, II>(d_mwh + (size_t)m0 * II, 0,
                        d_maph + (size_t)n0 * II, 0, sb, acc);

    int lane = threadIdx.x & 31, wid = threadIdx.x >> 5;
    int wm = wid & 1, wn = wid >> 1;
    #pragma unroll
    for (int mt = 0; mt < 4; mt++) {
        int cbase = m0 + wm * 64 + mt * 16 + (lane >> 2);
        #pragma unroll
        for (int nt = 0; nt < 4; nt++) {
            int qbase = n0 + wn * 32 + nt * 8 + (lane & 3) * 2;
            #pragma unroll
            for (int h = 0; h < 2; h++) {
                int c = cbase + h * 8;
                #pragma unroll
                for (int j = 0; j < 2; j++) {
                    int q = qbase + j;
                    int b = q / 49;
                    int n = q - b * 49;
                    size_t idx = ((size_t)b * CC + c) * NN + n;
                    out[idx] = x[idx] + d_sp[q] * acc[mt][nt][h * 2 + j];
                }
            }
        }
    }
}

// ---------------- K3: attention per batch (fp32), writes map hi ---------------
__global__ void __launch_bounds__(256) k_attn() {
    __shared__ float th_s[4][49][17];
    __shared__ float ph_s[4][49][17];
    __shared__ float sc[49][52];

    const float* gx = d_proj;
    const float* tx = d_proj + (size_t)BN * II;
    const float* px = d_proj + (size_t)2 * BN * II;

    int b = blockIdx.x;
    int tid = threadIdx.x;
    int g = tid >> 6, t = tid & 63;
    int ng = t >> 3, mg = t & 7;
    bool act = (ng < 7) && (mg < 7);

    float acc[7][7] = {};
    for (int kt = 0; kt < 16; kt++) {
        int kb = g * 256 + kt * 16;
        for (int e = t; e < 49 * 16; e += 64) {
            int r = e >> 4, kk = e & 15;
            th_s[g][r][kk] = tx[((size_t)b * NN + r) * II + kb + kk];
            ph_s[g][r][kk] = px[((size_t)b * NN + r) * II + kb + kk];
        }
        __syncthreads();
        if (act) {
            #pragma unroll
            for (int kk = 0; kk < 16; kk++) {
                float av[7], bv[7];
                #pragma unroll
                for (int i = 0; i < 7; i++) av[i] = th_s[g][ng * 7 + i][kk];
                #pragma unroll
                for (int j = 0; j < 7; j++) bv[j] = ph_s[g][mg * 7 + j][kk];
                #pragma unroll
                for (int i = 0; i < 7; i++)
                    #pragma unroll
                    for (int j = 0; j < 7; j++)
                        acc[i][j] += av[i] * bv[j];
            }
        }
        __syncthreads();
    }
    for (int gg = 0; gg < 4; gg++) {
        if (g == gg && act) {
            #pragma unroll
            for (int i = 0; i < 7; i++)
                #pragma unroll
                for (int j = 0; j < 7; j++) {
                    if (gg == 0) sc[ng * 7 + i][mg * 7 + j] = acc[i][j];
                    else         sc[ng * 7 + i][mg * 7 + j] += acc[i][j];
                }
        }
        __syncthreads();
    }
    if (tid < 49) {
        float mx = -1e30f;
        for (int m = 0; m < NN; m++) mx = fmaxf(mx, sc[tid][m]);
        float s = 0.f;
        for (int m = 0; m < NN; m++) {
            float e = expf(sc[tid][m] - mx);
            sc[tid][m] = e; s += e;
        }
        float inv = 1.f / s;
        for (int m = 0; m < NN; m++) sc[tid][m] *= inv;
    }
    __syncthreads();
    for (int op = 0; op < 4; op++) {
        int o = op * 256 + tid;
        float a2[49];
        #pragma unroll
        for (int n = 0; n < NN; n++) a2[n] = 0.f;
        for (int m = 0; m < NN; m++) {
            float gv = gx[((size_t)b * NN + m) * II + o];
            #pragma unroll
            for (int n = 0; n < NN; n++) a2[n] += sc[n][m] * gv;
        }
        for (int n = 0; n < NN; n++)
            d_maph[((size_t)b * NN + n) * II + o] = __float2half_rn(a2[n]);
    }
}

// ---------------- K4: spatial FC partials (32 batches/block, KSPL=32) ---------
__global__ void __launch_bounds__(256) k_spart(const float* __restrict__ x,
                                               const float* __restrict__ fcw) {
    __shared__ float fc_s[49][65];
    __shared__ float x_s[32][65];
    int b0 = blockIdx.x * 32;
    int ks = blockIdx.y;
    int tid = threadIdx.x;
    int bg = tid >> 5, jg = tid & 31;
    float acc[4][2] = {};
    for (int kc = 0; kc < KPER / 64; kc++) {
        int kb = ks * KPER + kc * 64;
        for (int e = tid; e < 49 * 64; e += 256) {
            int j = e >> 6, kk = e & 63;
            fc_s[j][kk] = fcw[(size_t)j * CN + kb + kk];
        }
        for (int e = tid; e < 32 * 64; e += 256) {
            int bl = e >> 6, kk = e & 63;
            x_s[bl][kk] = x[(size_t)(b0 + bl) * CN + kb + kk];
        }
        __syncthreads();
        #pragma unroll 4
        for (int kk = 0; kk < 64; kk++) {
            float f0 = fc_s[jg][kk];
            float f1 = (jg < 17) ? fc_s[jg + 32][kk] : 0.f;
            #pragma unroll
            for (int i = 0; i < 4; i++) {
                float xv = x_s[bg * 4 + i][kk];
                acc[i][0] += xv * f0; acc[i][1] += xv * f1;
            }
        }
        __syncthreads();
    }
    #pragma unroll
    for (int i = 0; i < 4; i++) {
        int b = b0 + bg * 4 + i;
        d_spart[((size_t)ks * BB + b) * NN + jg] = acc[i][0];
        if (jg + 32 < NN)
            d_spart[((size_t)ks * BB + b) * NN + jg + 32] = acc[i][1];
    }
}

// ---------------- K5: reduce k-split partials + bias --------------------------
__global__ void k_sred(const float* __restrict__ fcb) {
    int b = blockIdx.x, j = threadIdx.x;
    if (j < NN) {
        float s = fcb[j];
        for (int ks = 0; ks < KSPL; ks++)
            s += d_spart[((size_t)ks * BB + b) * NN + j];
        d_sp[b * NN + j] = s;
    }
}

// ---------------------------------------------------------------------------
extern "C" void kernel_launch(void* const* d_in, const int* in_sizes, int n_in,
                              void* d_out, int out_size) {
    const float* x    = (const float*)d_in[0];
    const float* g_w  = (const float*)d_in[1];
    const float* g_b  = (const float*)d_in[2];
    const float* th_w = (const float*)d_in[3];
    const float* th_b = (const float*)d_in[4];
    const float* ph_w = (const float*)d_in[5];
    const float* ph_b = (const float*)d_in[6];
    const float* W_w  = (const float*)d_in[7];
    const float* fc_w = (const float*)d_in[8];
    const float* fc_b = (const float*)d_in[9];
    float* out = (float*)d_out;
    (void)in_sizes; (void)n_in; (void)out_size;

    __half *p_wh, *p_wl, *p_mwh;
    float* p_proj;
    cudaGetSymbolAddress((void**)&p_wh,  d_wh);
    cudaGetSymbolAddress((void**)&p_wl,  d_wl);
    cudaGetSymbolAddress((void**)&p_mwh, d_mwh);
    cudaGetSymbolAddress((void**)&p_proj, d_proj);
    const ptrdiff_t DWL = p_wl - p_wh;

    const int SM3 = 3 * 4 * 8192;   // 96KB  (2 CTAs -> 192KB/SM)
    const int SM1 = 4 * 2 * 8192;   // 64KB  (2 CTAs -> 128KB/SM)
    cudaFuncSetAttribute(k_proj_mma<3, 3>, cudaFuncAttributeMaxDynamicSharedMemorySize, SM3);
    cudaFuncSetAttribute(k_proj_mma<1, 4>, cudaFuncAttributeMaxDynamicSharedMemorySize, SM1);
    cudaFuncSetAttribute(k_mask_mma,       cudaFuncAttributeMaxDynamicSharedMemorySize, SM1);

    const int WSZ = II * CC;  // 2M
    // launch order chosen so ncu -s 5 -c 1 captures k_proj_mma<3> (theta)
    k_split <<<(WSZ + 255) / 256, 256>>>(th_w, p_wh + WSZ,     p_wl + WSZ,     WSZ);
    k_split <<<(WSZ + 255) / 256, 256>>>(ph_w, p_wh + 2 * WSZ, p_wl + 2 * WSZ, WSZ);
    k_split1<<<(WSZ + 255) / 256, 256>>>(g_w,  p_wh, WSZ);
    k_split1<<<(WSZ + 255) / 256, 256>>>(W_w,  p_mwh, WSZ);

    k_transpose_split<<<dim3(CC / 64, BB), 256>>>(x);

    dim3 pg(II / 128, BN / 128);   // (8, 98)
    k_proj_mma<3, 3><<<pg, 256, SM3>>>(p_wh + WSZ,     DWL, th_b, p_proj + (size_t)BN * II);
    k_proj_mma<3, 3><<<pg, 256, SM3>>>(p_wh + 2 * WSZ, DWL, ph_b, p_proj + (size_t)2 * BN * II);
    k_proj_mma<1, 4><<<pg, 256, SM1>>>(p_wh,           0,   g_b,  p_proj);

    k_attn<<<BB, 256>>>();

    k_spart<<<dim3(BB / 32, KSPL), 256>>>(x, fc_w);
    k_sred<<<BB, 64>>>(fc_b);

    k_mask_mma<<<dim3(BN / 128, CC / 128), 256, SM1>>>(x, out);
}

// round 10
// speedup vs baseline: 3.9299x; 1.1492x over previous
#include <cuda_runtime.h>
#include <cuda_fp16.h>

// ---------------------------------------------------------------------------
// ModulatedAttLayer  B=256, C=2048, H=W=7 (N=49), INTER=1024
//
// R10: R8 kernels restructured as fused "fat kernels" (role = block range)
//      to get multi-stream-style overlap on ONE stream (graph/alloc legal):
//   k_prep : transpose+split(x) || 4 weight splits
//   k_mega : theta-proj || phi-proj || g-proj || spatial-FC partials
//   k_post : attention || sred
//   k_mask : mask GEMM + epilogue
// ---------------------------------------------------------------------------

#define BB   256
#define CC   2048
#define NN   49
#define II   1024
#define BN   (BB*NN)      // 12544
#define CN   (CC*NN)      // 100352
#define KSPL 32
#define KPER (CN/KSPL)    // 3136
#define WSZ  (II*CC)      // 2097152

__device__ __align__(16) __half d_xh[(size_t)BN*CC];   // xT hi
__device__ __align__(16) __half d_xl[(size_t)BN*CC];   // xT lo
__device__ __align__(16) __half d_wh[(size_t)3*II*CC]; // theta/phi/g weights hi
__device__ __align__(16) __half d_wl[(size_t)3*II*CC]; // lo (theta/phi used)
__device__ __align__(16) __half d_mwh[(size_t)CC*II];  // W_w hi
__device__ __align__(16) __half d_maph[(size_t)BN*II]; // map hi
__device__ float d_proj[(size_t)3*BN*II];              // tx/px/gx fp32
__device__ float d_spart[(size_t)KSPL*BB*NN];
__device__ float d_sp[(size_t)BB*NN];

// ---------------- helpers ----------------------------------------------------
__device__ __forceinline__ void splith(float v, __half& h, __half& l) {
    h = __float2half_rn(v);
    l = __float2half_rn(v - __half2float(h));
}

__device__ __forceinline__ void mma16(float* d, const unsigned* a, const unsigned* b) {
    asm volatile(
        "mma.sync.aligned.m16n8k16.row.col.f32.f16.f16.f32 "
        "{%0,%1,%2,%3}, {%4,%5,%6,%7}, {%8,%9}, {%0,%1,%2,%3};\n"
        : "+f"(d[0]), "+f"(d[1]), "+f"(d[2]), "+f"(d[3])
        : "r"(a[0]), "r"(a[1]), "r"(a[2]), "r"(a[3]), "r"(b[0]), "r"(b[1]));
}

__device__ __forceinline__ void cpa16s(unsigned s, const __half* g) {
    asm volatile("cp.async.cg.shared.global [%0], [%1], 16;\n" :: "r"(s), "l"(g));
}
__device__ __forceinline__ void cpcommit() { asm volatile("cp.async.commit_group;\n"); }
template<int N>
__device__ __forceinline__ void cpwaitN() {
    asm volatile("cp.async.wait_group %0;\n" :: "n"(N) : "memory");
}
__device__ __forceinline__ void ldsm4(unsigned& r0, unsigned& r1, unsigned& r2,
                                      unsigned& r3, unsigned addr) {
    asm volatile("ldmatrix.sync.aligned.m8n8.x4.shared.b16 {%0,%1,%2,%3}, [%4];"
                 : "=r"(r0), "=r"(r1), "=r"(r2), "=r"(r3) : "r"(addr));
}

// ---------------- GEMM core: acc[m,n] += A[m,k]*B[n,k] ------------------------
template<int NSPLIT, int STAGES, int K>
__device__ __forceinline__ void gemm_core(
    const __half* __restrict__ A, ptrdiff_t dAl,
    const __half* __restrict__ B, ptrdiff_t dBl,
    unsigned sb, float acc[4][4][4])
{
    constexpr int TILB = 128 * 32 * 2;   // tile bytes (8KB)
    constexpr int STB  = ((NSPLIT == 3) ? 4 : 2) * TILB;
    constexpr int T    = K / 32;
    const int tid = threadIdx.x, lane = tid & 31, wid = tid >> 5;
    const int wm = wid & 1, wn = wid >> 1;

    const int r0 = tid >> 2, ch = tid & 3, r1 = r0 + 64;
    const unsigned d0 = (unsigned)(r0 * 64 + ((ch ^ ((r0 >> 1) & 3)) << 4));
    const unsigned d1 = (unsigned)(r1 * 64 + ((ch ^ ((r1 >> 1) & 3)) << 4));
    const __half* a0p = A + (size_t)r0 * K + ch * 8;
    const __half* a1p = A + (size_t)r1 * K + ch * 8;
    const __half* b0p = B + (size_t)r0 * K + ch * 8;
    const __half* b1p = B + (size_t)r1 * K + ch * 8;

    auto issue = [&](int s, int t) {
        if (t < T) {
            unsigned st = sb + (unsigned)s * STB;
            int ko = t * 32;
            cpa16s(st + d0, a0p + ko);
            cpa16s(st + d1, a1p + ko);
            cpa16s(st + TILB + d0, b0p + ko);
            cpa16s(st + TILB + d1, b1p + ko);
            if (NSPLIT == 3) {
                cpa16s(st + 2 * TILB + d0, a0p + dAl + ko);
                cpa16s(st + 2 * TILB + d1, a1p + dAl + ko);
                cpa16s(st + 3 * TILB + d0, b0p + dBl + ko);
                cpa16s(st + 3 * TILB + d1, b1p + dBl + ko);
            }
        }
        cpcommit();
    };

    const int rr8 = ((lane >> 3) & 1) * 8 + (lane & 7);
    const int qh = lane >> 4;
    int aoff[4], asw[4], boff[2], bsw[2];
    #pragma unroll
    for (int mt = 0; mt < 4; mt++) {
        int mr = wm * 64 + mt * 16 + rr8;
        asw[mt] = (mr >> 1) & 3;
        aoff[mt] = mr * 64;
    }
    #pragma unroll
    for (int p = 0; p < 2; p++) {
        int nr = wn * 32 + p * 16 + rr8;
        bsw[p] = (nr >> 1) & 3;
        boff[p] = nr * 64;
    }

    #pragma unroll
    for (int s = 0; s < STAGES - 1; s++) issue(s, s);

    for (int t = 0; t < T; t++) {
        cpwaitN<STAGES - 2>();
        __syncthreads();
        issue((t + STAGES - 1) % STAGES, t + STAGES - 1);

        unsigned bse = sb + (unsigned)(t % STAGES) * STB;
        unsigned tA  = bse, tB = bse + TILB;
        unsigned tAl = bse + 2 * TILB, tBl = bse + 3 * TILB;

        #pragma unroll
        for (int ks = 0; ks < 2; ks++) {
            int kc = ks * 2 + qh;
            unsigned bh[4][2], bl[4][2];
            #pragma unroll
            for (int p = 0; p < 2; p++) {
                unsigned off = (unsigned)(boff[p] + ((kc ^ bsw[p]) << 4));
                unsigned q0, q1, q2, q3;
                ldsm4(q0, q1, q2, q3, tB + off);
                bh[2 * p][0] = q0; bh[2 * p + 1][0] = q1;
                bh[2 * p][1] = q2; bh[2 * p + 1][1] = q3;
                if (NSPLIT == 3) {
                    ldsm4(q0, q1, q2, q3, tBl + off);
                    bl[2 * p][0] = q0; bl[2 * p + 1][0] = q1;
                    bl[2 * p][1] = q2; bl[2 * p + 1][1] = q3;
                }
            }
            #pragma unroll
            for (int mt = 0; mt < 4; mt++) {
                unsigned off = (unsigned)(aoff[mt] + ((kc ^ asw[mt]) << 4));
                unsigned ah[4], al[4];
                ldsm4(ah[0], ah[1], ah[2], ah[3], tA + off);
                if (NSPLIT == 3)
                    ldsm4(al[0], al[1], al[2], al[3], tAl + off);
                #pragma unroll
                for (int nt = 0; nt < 4; nt++) {
                    if (NSPLIT == 3) {
                        mma16(acc[mt][nt], al, bh[nt]);
                        mma16(acc[mt][nt], ah, bl[nt]);
                    }
                    mma16(acc[mt][nt], ah, bh[nt]);
                }
            }
        }
    }
}

__device__ __forceinline__ void proj_epilogue(float acc[4][4][4],
                                              const float* __restrict__ bias,
                                              float* __restrict__ out,
                                              int m0, int n0) {
    int lane = threadIdx.x & 31, wid = threadIdx.x >> 5;
    int wm = wid & 1, wn = wid >> 1;
    #pragma unroll
    for (int mt = 0; mt < 4; mt++) {
        int r = m0 + wm * 64 + mt * 16 + (lane >> 2);
        #pragma unroll
        for (int nt = 0; nt < 4; nt++) {
            int c = n0 + wn * 32 + nt * 8 + (lane & 3) * 2;
            float b0 = bias[c], b1 = bias[c + 1];
            *(float2*)(out + (size_t)r * II + c) =
                make_float2(acc[mt][nt][0] + b0, acc[mt][nt][1] + b1);
            *(float2*)(out + (size_t)(r + 8) * II + c) =
                make_float2(acc[mt][nt][2] + b0, acc[mt][nt][3] + b1);
        }
    }
}

// ---------------- K_prep: transpose+split(x) || weight splits -----------------
// blocks [0,8192)        : transpose+split x
// blocks [8192,16384)    : split theta_w  -> d_wh+0*WSZ / d_wl+0*WSZ
// blocks [16384,24576)   : split phi_w    -> +1*WSZ
// blocks [24576,32768)   : split1 g_w     -> +2*WSZ
// blocks [32768,40960)   : split1 W_w     -> d_mwh
__global__ void __launch_bounds__(256) k_prep(const float* __restrict__ x,
                                              const float* __restrict__ th_w,
                                              const float* __restrict__ ph_w,
                                              const float* __restrict__ g_w,
                                              const float* __restrict__ W_w) {
    __shared__ float s[64][50];
    int bx = blockIdx.x;
    if (bx < 8192) {
        int b = bx >> 5, c0 = (bx & 31) * 64;
        const float* xb = x + (size_t)b * CN;
        for (int e = threadIdx.x; e < 64 * NN; e += 256) {
            int cl = e / NN, n = e - cl * NN;
            s[cl][n] = xb[(c0 + cl) * NN + n];
        }
        __syncthreads();
        for (int e = threadIdx.x; e < 64 * NN; e += 256) {
            int n = e >> 6, cl = e & 63;
            size_t o = ((size_t)b * NN + n) * CC + c0 + cl;
            splith(s[cl][n], d_xh[o], d_xl[o]);
        }
    } else {
        int role = (bx - 8192) >> 13;          // 0..3
        int i = ((bx - 8192) & 8191) * 256 + threadIdx.x;
        if (role == 0)      splith(th_w[i], d_wh[i],           d_wl[i]);
        else if (role == 1) splith(ph_w[i], d_wh[WSZ + i],     d_wl[WSZ + i]);
        else if (role == 2) d_wh[2 * (size_t)WSZ + i] = __float2half_rn(g_w[i]);
        else                d_mwh[i] = __float2half_rn(W_w[i]);
    }
}

// ---------------- K_mega: 3 projections || spatial-FC partials ----------------
// blocks [0,784)      : theta proj (NSPLIT=3) -> d_proj + 0
// blocks [784,1568)   : phi   proj (NSPLIT=3) -> d_proj + BN*II
// blocks [1568,2352)  : g     proj (NSPLIT=1) -> d_proj + 2*BN*II
// blocks [2352,2608)  : spart
__global__ void __launch_bounds__(256, 2) k_mega(const float* __restrict__ x,
                                                 const float* __restrict__ fcw,
                                                 const float* __restrict__ th_b,
                                                 const float* __restrict__ ph_b,
                                                 const float* __restrict__ g_b) {
    extern __shared__ __align__(16) __half sdyn[];
    unsigned sb = (unsigned)__cvta_generic_to_shared(sdyn);
    int bid = blockIdx.x;

    if (bid < 2352) {
        int role = bid / 784;          // 0 theta, 1 phi, 2 g
        int lb = bid - role * 784;
        int n0 = (lb & 7) * 128, m0 = (lb >> 3) * 128;
        const ptrdiff_t DXL = d_xl - d_xh;
        const ptrdiff_t DWL = d_wl - d_wh;
        float acc[4][4][4] = {};
        if (role < 2) {
            const __half* wh = d_wh + (size_t)role * WSZ + (size_t)n0 * CC;
            gemm_core<3, 3, CC>(d_xh + (size_t)m0 * CC, DXL, wh, DWL, sb, acc);
            proj_epilogue(acc, role == 0 ? th_b : ph_b,
                          d_proj + (size_t)role * BN * II, m0, n0);
        } else {
            const __half* wh = d_wh + 2 * (size_t)WSZ + (size_t)n0 * CC;
            gemm_core<1, 4, CC>(d_xh + (size_t)m0 * CC, 0, wh, 0, sb, acc);
            proj_epilogue(acc, g_b, d_proj + 2 * (size_t)BN * II, m0, n0);
        }
    } else {
        // --- spatial FC partials (dynamic smem reuse) ---
        int sid = bid - 2352;
        int b0 = (sid & 7) * 32;
        int ks = sid >> 3;
        float* fc_s = (float*)sdyn;              // [49][65]
        float* x_s  = fc_s + 49 * 65;            // [32][65]
        int tid = threadIdx.x;
        int bg = tid >> 5, jg = tid & 31;
        float acc[4][2] = {};
        for (int kc = 0; kc < KPER / 64; kc++) {
            int kb = ks * KPER + kc * 64;
            for (int e = tid; e < 49 * 64; e += 256) {
                int j = e >> 6, kk = e & 63;
                fc_s[j * 65 + kk] = fcw[(size_t)j * CN + kb + kk];
            }
            for (int e = tid; e < 32 * 64; e += 256) {
                int bl = e >> 6, kk = e & 63;
                x_s[bl * 65 + kk] = x[(size_t)(b0 + bl) * CN + kb + kk];
            }
            __syncthreads();
            #pragma unroll 4
            for (int kk = 0; kk < 64; kk++) {
                float f0 = fc_s[jg * 65 + kk];
                float f1 = (jg < 17) ? fc_s[(jg + 32) * 65 + kk] : 0.f;
                #pragma unroll
                for (int i = 0; i < 4; i++) {
                    float xv = x_s[(bg * 4 + i) * 65 + kk];
                    acc[i][0] += xv * f0; acc[i][1] += xv * f1;
                }
            }
            __syncthreads();
        }
        #pragma unroll
        for (int i = 0; i < 4; i++) {
            int b = b0 + bg * 4 + i;
            d_spart[((size_t)ks * BB + b) * NN + jg] = acc[i][0];
            if (jg + 32 < NN)
                d_spart[((size_t)ks * BB + b) * NN + jg + 32] = acc[i][1];
        }
    }
}

// ---------------- K_post: attention || sred ------------------------------------
__global__ void __launch_bounds__(256) k_post(const float* __restrict__ fcb) {
    __shared__ float th_s[4][49][17];
    __shared__ float ph_s[4][49][17];
    __shared__ float sc[49][52];

    if (blockIdx.x >= BB) {   // --- sred ---
        int b = blockIdx.x - BB, j = threadIdx.x;
        if (j < NN) {
            float s = fcb[j];
            for (int ks = 0; ks < KSPL; ks++)
                s += d_spart[((size_t)ks * BB + b) * NN + j];
            d_sp[b * NN + j] = s;
        }
        return;
    }

    // --- attention (batch = blockIdx.x) ---
    const float* tx = d_proj;
    const float* px = d_proj + (size_t)BN * II;
    const float* gx = d_proj + (size_t)2 * BN * II;

    int b = blockIdx.x;
    int tid = threadIdx.x;
    int g = tid >> 6, t = tid & 63;
    int ng = t >> 3, mg = t & 7;
    bool act = (ng < 7) && (mg < 7);

    float acc[7][7] = {};
    for (int kt = 0; kt < 16; kt++) {
        int kb = g * 256 + kt * 16;
        for (int e = t; e < 49 * 16; e += 64) {
            int r = e >> 4, kk = e & 15;
            th_s[g][r][kk] = tx[((size_t)b * NN + r) * II + kb + kk];
            ph_s[g][r][kk] = px[((size_t)b * NN + r) * II + kb + kk];
        }
        __syncthreads();
        if (act) {
            #pragma unroll
            for (int kk = 0; kk < 16; kk++) {
                float av[7], bv[7];
                #pragma unroll
                for (int i = 0; i < 7; i++) av[i] = th_s[g][ng * 7 + i][kk];
                #pragma unroll
                for (int j = 0; j < 7; j++) bv[j] = ph_s[g][mg * 7 + j][kk];
                #pragma unroll
                for (int i = 0; i < 7; i++)
                    #pragma unroll
                    for (int j = 0; j < 7; j++)
                        acc[i][j] += av[i] * bv[j];
            }
        }
        __syncthreads();
    }
    for (int gg = 0; gg < 4; gg++) {
        if (g == gg && act) {
            #pragma unroll
            for (int i = 0; i < 7; i++)
                #pragma unroll
                for (int j = 0; j < 7; j++) {
                    if (gg == 0) sc[ng * 7 + i][mg * 7 + j] = acc[i][j];
                    else         sc[ng * 7 + i][mg * 7 + j] += acc[i][j];
                }
        }
        __syncthreads();
    }
    if (tid < 49) {
        float mx = -1e30f;
        for (int m = 0; m < NN; m++) mx = fmaxf(mx, sc[tid][m]);
        float s = 0.f;
        for (int m = 0; m < NN; m++) {
            float e = expf(sc[tid][m] - mx);
            sc[tid][m] = e; s += e;
        }
        float inv = 1.f / s;
        for (int m = 0; m < NN; m++) sc[tid][m] *= inv;
    }
    __syncthreads();
    for (int op = 0; op < 4; op++) {
        int o = op * 256 + tid;
        float a2[49];
        #pragma unroll
        for (int n = 0; n < NN; n++) a2[n] = 0.f;
        for (int m = 0; m < NN; m++) {
            float gv = gx[((size_t)b * NN + m) * II + o];
            #pragma unroll
            for (int n = 0; n < NN; n++) a2[n] += sc[n][m] * gv;
        }
        for (int n = 0; n < NN; n++)
            d_maph[((size_t)b * NN + n) * II + o] = __float2half_rn(a2[n]);
    }
}

// ---------------- K_mask: mask GEMM + epilogue (M=2048, N=B*49, K=1024) -------
__global__ void __launch_bounds__(256, 2) k_mask_mma(const float* __restrict__ x,
                                                     float* __restrict__ out) {
    extern __shared__ __align__(16) __half sdyn[];
    unsigned sb = (unsigned)__cvta_generic_to_shared(sdyn);
    int n0 = blockIdx.x * 128;
    int m0 = blockIdx.y * 128;
    float acc[4][4][4] = {};
    gemm_core<1, 4, II>(d_mwh + (size_t)m0 * II, 0,
                        d_maph + (size_t)n0 * II, 0, sb, acc);

    int lane = threadIdx.x & 31, wid = threadIdx.x >> 5;
    int wm = wid & 1, wn = wid >> 1;
    #pragma unroll
    for (int mt = 0; mt < 4; mt++) {
        int cbase = m0 + wm * 64 + mt * 16 + (lane >> 2);
        #pragma unroll
        for (int nt = 0; nt < 4; nt++) {
            int qbase = n0 + wn * 32 + nt * 8 + (lane & 3) * 2;
            #pragma unroll
            for (int h = 0; h < 2; h++) {
                int c = cbase + h * 8;
                #pragma unroll
                for (int j = 0; j < 2; j++) {
                    int q = qbase + j;
                    int b = q / 49;
                    int n = q - b * 49;
                    size_t idx = ((size_t)b * CC + c) * NN + n;
                    out[idx] = x[idx] + d_sp[q] * acc[mt][nt][h * 2 + j];
                }
            }
        }
    }
}

// ---------------------------------------------------------------------------
extern "C" void kernel_launch(void* const* d_in, const int* in_sizes, int n_in,
                              void* d_out, int out_size) {
    const float* x    = (const float*)d_in[0];
    const float* g_w  = (const float*)d_in[1];
    const float* g_b  = (const float*)d_in[2];
    const float* th_w = (const float*)d_in[3];
    const float* th_b = (const float*)d_in[4];
    const float* ph_w = (const float*)d_in[5];
    const float* ph_b = (const float*)d_in[6];
    const float* W_w  = (const float*)d_in[7];
    const float* fc_w = (const float*)d_in[8];
    const float* fc_b = (const float*)d_in[9];
    float* out = (float*)d_out;
    (void)in_sizes; (void)n_in; (void)out_size;

    const int SM3 = 3 * 4 * 8192;   // 96KB
    const int SM1 = 4 * 2 * 8192;   // 64KB
    cudaFuncSetAttribute(k_mega,     cudaFuncAttributeMaxDynamicSharedMemorySize, SM3);
    cudaFuncSetAttribute(k_mask_mma, cudaFuncAttributeMaxDynamicSharedMemorySize, SM1);

    k_prep<<<40960, 256>>>(x, th_w, ph_w, g_w, W_w);
    k_mega<<<2608, 256, SM3>>>(x, fc_w, th_b, ph_b, g_b);
    k_post<<<2 * BB, 256>>>(fc_b);
    k_mask_mma<<<dim3(BN / 128, CC / 128), 256, SM1>>>(x, out);
}

// round 11
// speedup vs baseline: 3.9577x; 1.0071x over previous
#include <cuda_runtime.h>
#include <cuda_fp16.h>

// ---------------------------------------------------------------------------
// ModulatedAttLayer  B=256, C=2048, H=W=7 (N=49), INTER=1024
//
// R11: R10 + memory hygiene:
//   k_prep : vectorized (float4 loads, 8B packed half stores)
//   k_mega : proj epilogues staged through smem (coalesced 512B runs)
//   k_mask : epilogue staged through smem (coalesced along n)
// ---------------------------------------------------------------------------

#define BB   256
#define CC   2048
#define NN   49
#define II   1024
#define BN   (BB*NN)      // 12544
#define CN   (CC*NN)      // 100352
#define KSPL 32
#define KPER (CN/KSPL)    // 3136
#define WSZ  (II*CC)      // 2097152

__device__ __align__(16) __half d_xh[(size_t)BN*CC];   // xT hi
__device__ __align__(16) __half d_xl[(size_t)BN*CC];   // xT lo
__device__ __align__(16) __half d_wh[(size_t)3*II*CC]; // theta/phi/g weights hi
__device__ __align__(16) __half d_wl[(size_t)3*II*CC]; // lo (theta/phi used)
__device__ __align__(16) __half d_mwh[(size_t)CC*II];  // W_w hi
__device__ __align__(16) __half d_maph[(size_t)BN*II]; // map hi
__device__ float d_proj[(size_t)3*BN*II];              // tx/px/gx fp32
__device__ float d_spart[(size_t)KSPL*BB*NN];
__device__ float d_sp[(size_t)BB*NN];

// ---------------- helpers ----------------------------------------------------
__device__ __forceinline__ void splith(float v, __half& h, __half& l) {
    h = __float2half_rn(v);
    l = __float2half_rn(v - __half2float(h));
}
__device__ __forceinline__ unsigned pack2(__half a, __half b) {
    __half2 t = __halves2half2(a, b);
    return *reinterpret_cast<unsigned*>(&t);
}

__device__ __forceinline__ void mma16(float* d, const unsigned* a, const unsigned* b) {
    asm volatile(
        "mma.sync.aligned.m16n8k16.row.col.f32.f16.f16.f32 "
        "{%0,%1,%2,%3}, {%4,%5,%6,%7}, {%8,%9}, {%0,%1,%2,%3};\n"
        : "+f"(d[0]), "+f"(d[1]), "+f"(d[2]), "+f"(d[3])
        : "r"(a[0]), "r"(a[1]), "r"(a[2]), "r"(a[3]), "r"(b[0]), "r"(b[1]));
}

__device__ __forceinline__ void cpa16s(unsigned s, const __half* g) {
    asm volatile("cp.async.cg.shared.global [%0], [%1], 16;\n" :: "r"(s), "l"(g));
}
__device__ __forceinline__ void cpcommit() { asm volatile("cp.async.commit_group;\n"); }
template<int N>
__device__ __forceinline__ void cpwaitN() {
    asm volatile("cp.async.wait_group %0;\n" :: "n"(N) : "memory");
}
__device__ __forceinline__ void ldsm4(unsigned& r0, unsigned& r1, unsigned& r2,
                                      unsigned& r3, unsigned addr) {
    asm volatile("ldmatrix.sync.aligned.m8n8.x4.shared.b16 {%0,%1,%2,%3}, [%4];"
                 : "=r"(r0), "=r"(r1), "=r"(r2), "=r"(r3) : "r"(addr));
}

// ---------------- GEMM core: acc[m,n] += A[m,k]*B[n,k] ------------------------
template<int NSPLIT, int STAGES, int K>
__device__ __forceinline__ void gemm_core(
    const __half* __restrict__ A, ptrdiff_t dAl,
    const __half* __restrict__ B, ptrdiff_t dBl,
    unsigned sb, float acc[4][4][4])
{
    constexpr int TILB = 128 * 32 * 2;   // tile bytes (8KB)
    constexpr int STB  = ((NSPLIT == 3) ? 4 : 2) * TILB;
    constexpr int T    = K / 32;
    const int tid = threadIdx.x, lane = tid & 31, wid = tid >> 5;
    const int wm = wid & 1, wn = wid >> 1;

    const int r0 = tid >> 2, ch = tid & 3, r1 = r0 + 64;
    const unsigned d0 = (unsigned)(r0 * 64 + ((ch ^ ((r0 >> 1) & 3)) << 4));
    const unsigned d1 = (unsigned)(r1 * 64 + ((ch ^ ((r1 >> 1) & 3)) << 4));
    const __half* a0p = A + (size_t)r0 * K + ch * 8;
    const __half* a1p = A + (size_t)r1 * K + ch * 8;
    const __half* b0p = B + (size_t)r0 * K + ch * 8;
    const __half* b1p = B + (size_t)r1 * K + ch * 8;

    auto issue = [&](int s, int t) {
        if (t < T) {
            unsigned st = sb + (unsigned)s * STB;
            int ko = t * 32;
            cpa16s(st + d0, a0p + ko);
            cpa16s(st + d1, a1p + ko);
            cpa16s(st + TILB + d0, b0p + ko);
            cpa16s(st + TILB + d1, b1p + ko);
            if (NSPLIT == 3) {
                cpa16s(st + 2 * TILB + d0, a0p + dAl + ko);
                cpa16s(st + 2 * TILB + d1, a1p + dAl + ko);
                cpa16s(st + 3 * TILB + d0, b0p + dBl + ko);
                cpa16s(st + 3 * TILB + d1, b1p + dBl + ko);
            }
        }
        cpcommit();
    };

    const int rr8 = ((lane >> 3) & 1) * 8 + (lane & 7);
    const int qh = lane >> 4;
    int aoff[4], asw[4], boff[2], bsw[2];
    #pragma unroll
    for (int mt = 0; mt < 4; mt++) {
        int mr = wm * 64 + mt * 16 + rr8;
        asw[mt] = (mr >> 1) & 3;
        aoff[mt] = mr * 64;
    }
    #pragma unroll
    for (int p = 0; p < 2; p++) {
        int nr = wn * 32 + p * 16 + rr8;
        bsw[p] = (nr >> 1) & 3;
        boff[p] = nr * 64;
    }

    #pragma unroll
    for (int s = 0; s < STAGES - 1; s++) issue(s, s);

    for (int t = 0; t < T; t++) {
        cpwaitN<STAGES - 2>();
        __syncthreads();
        issue((t + STAGES - 1) % STAGES, t + STAGES - 1);

        unsigned bse = sb + (unsigned)(t % STAGES) * STB;
        unsigned tA  = bse, tB = bse + TILB;
        unsigned tAl = bse + 2 * TILB, tBl = bse + 3 * TILB;

        #pragma unroll
        for (int ks = 0; ks < 2; ks++) {
            int kc = ks * 2 + qh;
            unsigned bh[4][2], bl[4][2];
            #pragma unroll
            for (int p = 0; p < 2; p++) {
                unsigned off = (unsigned)(boff[p] + ((kc ^ bsw[p]) << 4));
                unsigned q0, q1, q2, q3;
                ldsm4(q0, q1, q2, q3, tB + off);
                bh[2 * p][0] = q0; bh[2 * p + 1][0] = q1;
                bh[2 * p][1] = q2; bh[2 * p + 1][1] = q3;
                if (NSPLIT == 3) {
                    ldsm4(q0, q1, q2, q3, tBl + off);
                    bl[2 * p][0] = q0; bl[2 * p + 1][0] = q1;
                    bl[2 * p][1] = q2; bl[2 * p + 1][1] = q3;
                }
            }
            #pragma unroll
            for (int mt = 0; mt < 4; mt++) {
                unsigned off = (unsigned)(aoff[mt] + ((kc ^ asw[mt]) << 4));
                unsigned ah[4], al[4];
                ldsm4(ah[0], ah[1], ah[2], ah[3], tA + off);
                if (NSPLIT == 3)
                    ldsm4(al[0], al[1], al[2], al[3], tAl + off);
                #pragma unroll
                for (int nt = 0; nt < 4; nt++) {
                    if (NSPLIT == 3) {
                        mma16(acc[mt][nt], al, bh[nt]);
                        mma16(acc[mt][nt], ah, bl[nt]);
                    }
                    mma16(acc[mt][nt], ah, bh[nt]);
                }
            }
        }
    }
}

// stage acc tile into smem [128][132] (row = m/c local, col = n/q local)
__device__ __forceinline__ void stage_acc(float acc[4][4][4], float* stage) {
    int lane = threadIdx.x & 31, wid = threadIdx.x >> 5;
    int wm = wid & 1, wn = wid >> 1;
    #pragma unroll
    for (int mt = 0; mt < 4; mt++) {
        #pragma unroll
        for (int nt = 0; nt < 4; nt++) {
            #pragma unroll
            for (int h = 0; h < 2; h++) {
                int ml = wm * 64 + mt * 16 + (lane >> 2) + h * 8;
                #pragma unroll
                for (int j = 0; j < 2; j++) {
                    int nl = wn * 32 + nt * 8 + (lane & 3) * 2 + j;
                    stage[ml * 132 + nl] = acc[mt][nt][h * 2 + j];
                }
            }
        }
    }
}

// ---------------- K_prep: transpose+split(x) || weight splits -----------------
// blocks [0,8192)              : transpose+split x (packed 8B stores)
// blocks [8192,8192+4*2048)    : weight splits, float4 loads
__global__ void __launch_bounds__(256) k_prep(const float* __restrict__ x,
                                              const float* __restrict__ th_w,
                                              const float* __restrict__ ph_w,
                                              const float* __restrict__ g_w,
                                              const float* __restrict__ W_w) {
    __shared__ float s[64][50];
    int bx = blockIdx.x;
    if (bx < 8192) {
        int b = bx >> 5, c0 = (bx & 31) * 64;
        const float* xb = x + (size_t)b * CN;
        for (int e = threadIdx.x; e < 64 * NN; e += 256) {
            int cl = e / NN, n = e - cl * NN;
            s[cl][n] = xb[(c0 + cl) * NN + n];
        }
        __syncthreads();
        // 16 groups of 4 channels x 49 n = 784 packed stores (8B each)
        for (int e = threadIdx.x; e < 16 * NN; e += 256) {
            int n = e >> 4, clg = (e & 15) * 4;
            __half h[4], l[4];
            #pragma unroll
            for (int k = 0; k < 4; k++) splith(s[clg + k][n], h[k], l[k]);
            size_t o = ((size_t)b * NN + n) * CC + c0 + clg;
            *reinterpret_cast<uint2*>(d_xh + o) =
                make_uint2(pack2(h[0], h[1]), pack2(h[2], h[3]));
            *reinterpret_cast<uint2*>(d_xl + o) =
                make_uint2(pack2(l[0], l[1]), pack2(l[2], l[3]));
        }
    } else {
        int role = (bx - 8192) >> 11;          // 0..3
        int idx = (((bx - 8192) & 2047) * 256 + threadIdx.x) * 4;
        if (role == 0) {
            float4 v = *reinterpret_cast<const float4*>(th_w + idx);
            __half h[4], l[4];
            splith(v.x, h[0], l[0]); splith(v.y, h[1], l[1]);
            splith(v.z, h[2], l[2]); splith(v.w, h[3], l[3]);
            *reinterpret_cast<uint2*>(d_wh + idx) =
                make_uint2(pack2(h[0], h[1]), pack2(h[2], h[3]));
            *reinterpret_cast<uint2*>(d_wl + idx) =
                make_uint2(pack2(l[0], l[1]), pack2(l[2], l[3]));
        } else if (role == 1) {
            float4 v = *reinterpret_cast<const float4*>(ph_w + idx);
            __half h[4], l[4];
            splith(v.x, h[0], l[0]); splith(v.y, h[1], l[1]);
            splith(v.z, h[2], l[2]); splith(v.w, h[3], l[3]);
            *reinterpret_cast<uint2*>(d_wh + WSZ + idx) =
                make_uint2(pack2(h[0], h[1]), pack2(h[2], h[3]));
            *reinterpret_cast<uint2*>(d_wl + WSZ + idx) =
                make_uint2(pack2(l[0], l[1]), pack2(l[2], l[3]));
        } else if (role == 2) {
            float4 v = *reinterpret_cast<const float4*>(g_w + idx);
            *reinterpret_cast<uint2*>(d_wh + 2 * (size_t)WSZ + idx) =
                make_uint2(pack2(__float2half_rn(v.x), __float2half_rn(v.y)),
                           pack2(__float2half_rn(v.z), __float2half_rn(v.w)));
        } else {
            float4 v = *reinterpret_cast<const float4*>(W_w + idx);
            *reinterpret_cast<uint2*>(d_mwh + idx) =
                make_uint2(pack2(__float2half_rn(v.x), __float2half_rn(v.y)),
                           pack2(__float2half_rn(v.z), __float2half_rn(v.w)));
        }
    }
}

// ---------------- K_mega: 3 projections || spatial-FC partials ----------------
__global__ void __launch_bounds__(256, 2) k_mega(const float* __restrict__ x,
                                                 const float* __restrict__ fcw,
                                                 const float* __restrict__ th_b,
                                                 const float* __restrict__ ph_b,
                                                 const float* __restrict__ g_b) {
    extern __shared__ __align__(16) __half sdyn[];
    unsigned sb = (unsigned)__cvta_generic_to_shared(sdyn);
    int bid = blockIdx.x;
    int tid = threadIdx.x;

    if (bid < 2352) {
        int role = bid / 784;          // 0 theta, 1 phi, 2 g
        int lb = bid - role * 784;
        int n0 = (lb & 7) * 128, m0 = (lb >> 3) * 128;
        const ptrdiff_t DXL = d_xl - d_xh;
        const ptrdiff_t DWL = d_wl - d_wh;
        float acc[4][4][4] = {};
        const float* bias;
        if (role < 2) {
            const __half* wh = d_wh + (size_t)role * WSZ + (size_t)n0 * CC;
            gemm_core<3, 3, CC>(d_xh + (size_t)m0 * CC, DXL, wh, DWL, sb, acc);
            bias = (role == 0) ? th_b : ph_b;
        } else {
            const __half* wh = d_wh + 2 * (size_t)WSZ + (size_t)n0 * CC;
            gemm_core<1, 4, CC>(d_xh + (size_t)m0 * CC, 0, wh, 0, sb, acc);
            bias = g_b;
        }
        float* out = d_proj + (size_t)role * BN * II;
        float* stage = (float*)sdyn;
        __syncthreads();
        stage_acc(acc, stage);
        __syncthreads();
        for (int e = tid; e < 128 * 128; e += 256) {
            int ml = e >> 7, ql = e & 127;
            out[(size_t)(m0 + ml) * II + n0 + ql] = stage[ml * 132 + ql] + bias[n0 + ql];
        }
    } else {
        // --- spatial FC partials ---
        int sid = bid - 2352;
        int b0 = (sid & 7) * 32;
        int ks = sid >> 3;
        float* fc_s = (float*)sdyn;              // [49][65]
        float* x_s  = fc_s + 49 * 65;            // [32][65]
        int bg = tid >> 5, jg = tid & 31;
        float acc[4][2] = {};
        for (int kc = 0; kc < KPER / 64; kc++) {
            int kb = ks * KPER + kc * 64;
            for (int e = tid; e < 49 * 64; e += 256) {
                int j = e >> 6, kk = e & 63;
                fc_s[j * 65 + kk] = fcw[(size_t)j * CN + kb + kk];
            }
            for (int e = tid; e < 32 * 64; e += 256) {
                int bl = e >> 6, kk = e & 63;
                x_s[bl * 65 + kk] = x[(size_t)(b0 + bl) * CN + kb + kk];
            }
            __syncthreads();
            #pragma unroll 4
            for (int kk = 0; kk < 64; kk++) {
                float f0 = fc_s[jg * 65 + kk];
                float f1 = (jg < 17) ? fc_s[(jg + 32) * 65 + kk] : 0.f;
                #pragma unroll
                for (int i = 0; i < 4; i++) {
                    float xv = x_s[(bg * 4 + i) * 65 + kk];
                    acc[i][0] += xv * f0; acc[i][1] += xv * f1;
                }
            }
            __syncthreads();
        }
        #pragma unroll
        for (int i = 0; i < 4; i++) {
            int b = b0 + bg * 4 + i;
            d_spart[((size_t)ks * BB + b) * NN + jg] = acc[i][0];
            if (jg + 32 < NN)
                d_spart[((size_t)ks * BB + b) * NN + jg + 32] = acc[i][1];
        }
    }
}

// ---------------- K_post: attention || sred ------------------------------------
__global__ void __launch_bounds__(256) k_post(const float* __restrict__ fcb) {
    __shared__ float th_s[4][49][17];
    __shared__ float ph_s[4][49][17];
    __shared__ float sc[49][52];

    if (blockIdx.x >= BB) {   // --- sred ---
        int b = blockIdx.x - BB, j = threadIdx.x;
        if (j < NN) {
            float s = fcb[j];
            for (int ks = 0; ks < KSPL; ks++)
                s += d_spart[((size_t)ks * BB + b) * NN + j];
            d_sp[b * NN + j] = s;
        }
        return;
    }

    const float* tx = d_proj;
    const float* px = d_proj + (size_t)BN * II;
    const float* gx = d_proj + (size_t)2 * BN * II;

    int b = blockIdx.x;
    int tid = threadIdx.x;
    int g = tid >> 6, t = tid & 63;
    int ng = t >> 3, mg = t & 7;
    bool act = (ng < 7) && (mg < 7);

    float acc[7][7] = {};
    for (int kt = 0; kt < 16; kt++) {
        int kb = g * 256 + kt * 16;
        for (int e = t; e < 49 * 16; e += 64) {
            int r = e >> 4, kk = e & 15;
            th_s[g][r][kk] = tx[((size_t)b * NN + r) * II + kb + kk];
            ph_s[g][r][kk] = px[((size_t)b * NN + r) * II + kb + kk];
        }
        __syncthreads();
        if (act) {
            #pragma unroll
            for (int kk = 0; kk < 16; kk++) {
                float av[7], bv[7];
                #pragma unroll
                for (int i = 0; i < 7; i++) av[i] = th_s[g][ng * 7 + i][kk];
                #pragma unroll
                for (int j = 0; j < 7; j++) bv[j] = ph_s[g][mg * 7 + j][kk];
                #pragma unroll
                for (int i = 0; i < 7; i++)
                    #pragma unroll
                    for (int j = 0; j < 7; j++)
                        acc[i][j] += av[i] * bv[j];
            }
        }
        __syncthreads();
    }
    for (int gg = 0; gg < 4; gg++) {
        if (g == gg && act) {
            #pragma unroll
            for (int i = 0; i < 7; i++)
                #pragma unroll
                for (int j = 0; j < 7; j++) {
                    if (gg == 0) sc[ng * 7 + i][mg * 7 + j] = acc[i][j];
                    else         sc[ng * 7 + i][mg * 7 + j] += acc[i][j];
                }
        }
        __syncthreads();
    }
    if (tid < 49) {
        float mx = -1e30f;
        for (int m = 0; m < NN; m++) mx = fmaxf(mx, sc[tid][m]);
        float s = 0.f;
        for (int m = 0; m < NN; m++) {
            float e = expf(sc[tid][m] - mx);
            sc[tid][m] = e; s += e;
        }
        float inv = 1.f / s;
        for (int m = 0; m < NN; m++) sc[tid][m] *= inv;
    }
    __syncthreads();
    for (int op = 0; op < 4; op++) {
        int o = op * 256 + tid;
        float a2[49];
        #pragma unroll
        for (int n = 0; n < NN; n++) a2[n] = 0.f;
        for (int m = 0; m < NN; m++) {
            float gv = gx[((size_t)b * NN + m) * II + o];
            #pragma unroll
            for (int n = 0; n < NN; n++) a2[n] += sc[n][m] * gv;
        }
        for (int n = 0; n < NN; n++)
            d_maph[((size_t)b * NN + n) * II + o] = __float2half_rn(a2[n]);
    }
}

// ---------------- K_mask: mask GEMM + staged epilogue --------------------------
__global__ void __launch_bounds__(256, 2) k_mask_mma(const float* __restrict__ x,
                                                     float* __restrict__ out) {
    extern __shared__ __align__(16) __half sdyn[];
    unsigned sb = (unsigned)__cvta_generic_to_shared(sdyn);
    int n0 = blockIdx.x * 128;   // q tile
    int m0 = blockIdx.y * 128;   // c tile
    int tid = threadIdx.x;
    float acc[4][4][4] = {};
    gemm_core<1, 4, II>(d_mwh + (size_t)m0 * II, 0,
                        d_maph + (size_t)n0 * II, 0, sb, acc);

    float* stage = (float*)sdyn;
    __syncthreads();
    stage_acc(acc, stage);
    __syncthreads();
    for (int e = tid; e < 128 * 128; e += 256) {
        int cl = e >> 7, ql = e & 127;
        int q = n0 + ql;
        int b = q / 49, n = q - b * 49;
        size_t idx = ((size_t)b * CC + m0 + cl) * NN + n;
        out[idx] = x[idx] + d_sp[q] * stage[cl * 132 + ql];
    }
}

// ---------------------------------------------------------------------------
extern "C" void kernel_launch(void* const* d_in, const int* in_sizes, int n_in,
                              void* d_out, int out_size) {
    const float* x    = (const float*)d_in[0];
    const float* g_w  = (const float*)d_in[1];
    const float* g_b  = (const float*)d_in[2];
    const float* th_w = (const float*)d_in[3];
    const float* th_b = (const float*)d_in[4];
    const float* ph_w = (const float*)d_in[5];
    const float* ph_b = (const float*)d_in[6];
    const float* W_w  = (const float*)d_in[7];
    const float* fc_w = (const float*)d_in[8];
    const float* fc_b = (const float*)d_in[9];
    float* out = (float*)d_out;
    (void)in_sizes; (void)n_in; (void)out_size;

    const int SM3 = 3 * 4 * 8192;                // 96KB  (>= 67.6KB stage)
    const int SMK = 128 * 132 * 4 > 4 * 2 * 8192 ? 128 * 132 * 4 : 4 * 2 * 8192; // 67584
    cudaFuncSetAttribute(k_mega,     cudaFuncAttributeMaxDynamicSharedMemorySize, SM3);
    cudaFuncSetAttribute(k_mask_mma, cudaFuncAttributeMaxDynamicSharedMemorySize, SMK);

    k_prep<<<8192 + 4 * 2048, 256>>>(x, th_w, ph_w, g_w, W_w);
    k_mega<<<2608, 256, SM3>>>(x, fc_w, th_b, ph_b, g_b);
    k_post<<<2 * BB, 256>>>(fc_b);
    k_mask_mma<<<dim3(BN / 128, CC / 128), 256, SMK>>>(x, out);
}